// round 1
// baseline (speedup 1.0000x reference)
#include <cuda_runtime.h>
#include <math.h>
#include <stdint.h>

#define N       10000
#define NFEAT   512
#define NHID    256
#define NCLASS  40
#define NLAYERS 8
#define MAXW    128     // max nnz per row incl. self loop (expected ~31, P(>100) ~ 0)

// ---------------- device scratch (no allocation allowed) ----------------
__device__ float g_dinv[N];
__device__ int   g_rowlen[N];
__device__ int   g_cols[(size_t)N * MAXW];
__device__ float g_h0[(size_t)N * NHID];
__device__ float g_h[(size_t)N * NHID];
__device__ float g_support[(size_t)N * NHID];

// ==========================================================================
// 1) Build ELL from dense binary adjacency. One block (256 thr) per row.
//    Deterministic in-order compaction via warp scans (no atomics -> the
//    later float sums have a fixed order -> bitwise reproducible output).
//    adj is exactly binary, so degree = count + 1 (self loop).
// ==========================================================================
__global__ void build_ell_kernel(const float* __restrict__ adj) {
    int i = blockIdx.x;
    const float* row = adj + (size_t)i * N;
    int tid = threadIdx.x, lane = tid & 31, wid = tid >> 5;
    __shared__ int s_wcnt[8];
    __shared__ int s_base;
    if (tid == 0) s_base = 0;
    __syncthreads();
    int rowoff = i * MAXW;

    for (int c0 = 0; c0 < N; c0 += 1024) {
        int c = c0 + tid * 4;
        float4 v = make_float4(0.f, 0.f, 0.f, 0.f);
        if (c + 3 < N) v = *(const float4*)(row + c);   // rows are 16B aligned (40000B)
        int p0 = (v.x != 0.f), p1 = (v.y != 0.f), p2 = (v.z != 0.f), p3 = (v.w != 0.f);
        int pcnt = p0 + p1 + p2 + p3;

        // warp inclusive scan of pcnt
        int x = pcnt;
        #pragma unroll
        for (int d = 1; d < 32; d <<= 1) {
            int y = __shfl_up_sync(0xffffffffu, x, d);
            if (lane >= d) x += y;
        }
        if (lane == 31) s_wcnt[wid] = x;
        __syncthreads();
        int wpre = 0, total = 0;
        #pragma unroll
        for (int w = 0; w < 8; w++) {
            int t = s_wcnt[w];
            if (w < wid) wpre += t;
            total += t;
        }
        int pos = s_base + wpre + (x - pcnt);   // exclusive position, in column order
        if (p0) { if (pos < MAXW - 1) g_cols[rowoff + pos] = c + 0; pos++; }
        if (p1) { if (pos < MAXW - 1) g_cols[rowoff + pos] = c + 1; pos++; }
        if (p2) { if (pos < MAXW - 1) g_cols[rowoff + pos] = c + 2; pos++; }
        if (p3) { if (pos < MAXW - 1) g_cols[rowoff + pos] = c + 3; pos++; }
        __syncthreads();
        if (tid == 0) s_base += total;
        __syncthreads();
    }
    if (tid == 0) {
        int cnt = s_base;
        if (cnt > MAXW - 1) cnt = MAXW - 1;
        g_cols[rowoff + cnt] = i;               // self loop appended last
        g_rowlen[i] = cnt + 1;
        g_dinv[i] = rsqrtf((float)(cnt + 1));   // degree of A+I is exact integer
    }
}

// ==========================================================================
// 2) SpMM fused with residual mix:
//    support[i,:] = 0.9 * dinv[i] * sum_k dinv[c_k] * h[c_k,:]  +  0.1 * h0[i,:]
//    One block per row, 256 threads = NHID features. Gathers hit L2 (h=10MB).
// ==========================================================================
__global__ void spmm_support_kernel(const float* __restrict__ h,
                                    float* __restrict__ support) {
    int i = blockIdx.x, tid = threadIdx.x;
    __shared__ float s_w[MAXW];
    __shared__ int   s_c[MAXW];
    int len = g_rowlen[i];
    if (tid < MAXW && tid < len) {
        int c = g_cols[i * MAXW + tid];
        s_c[tid] = c * NHID;
        s_w[tid] = g_dinv[c];
    }
    __syncthreads();
    float acc = 0.f;
    #pragma unroll 4
    for (int k = 0; k < len; k++)
        acc += s_w[k] * __ldg(&h[s_c[k] + tid]);
    support[(size_t)i * NHID + tid] =
        0.9f * g_dinv[i] * acc + 0.1f * g_h0[(size_t)i * NHID + tid];
}

// ==========================================================================
// 3) Tiled fp32 GEMM, 64x64x16 tiles, 4x4 register blocking, 256 threads.
//    mode 0: C = relu(A@B + bias)                       (input layer)
//    mode 1: C = relu(theta*(A@B) + rtheta*resid)       (GCNII layer)
// ==========================================================================
__global__ void gemm_epi_kernel(const float* __restrict__ A,
                                const float* __restrict__ B,
                                float* __restrict__ C,
                                int M, int K, int NC,
                                const float* __restrict__ bias,
                                const float* __restrict__ resid,
                                float theta, float rtheta, int mode) {
    __shared__ float As[16][64];   // transposed A tile: As[k][m]
    __shared__ float Bs[16][64];

    int tid = threadIdx.x;
    int tx = tid & 15, ty = tid >> 4;
    int bm = blockIdx.x * 64, bn = blockIdx.y * 64;

    float acc[4][4] = {};

    int la_m = tid >> 2;          // 0..63
    int la_k = (tid & 3) * 4;     // 0,4,8,12
    int lb_k = tid >> 4;          // 0..15
    int lb_n = (tid & 15) * 4;    // 0..60

    for (int k0 = 0; k0 < K; k0 += 16) {
        float4 av = make_float4(0.f, 0.f, 0.f, 0.f);
        int ar = bm + la_m;
        if (ar < M) av = *(const float4*)(A + (size_t)ar * K + k0 + la_k);
        As[la_k + 0][la_m] = av.x;
        As[la_k + 1][la_m] = av.y;
        As[la_k + 2][la_m] = av.z;
        As[la_k + 3][la_m] = av.w;

        float4 bv = *(const float4*)(B + (size_t)(k0 + lb_k) * NC + bn + lb_n);
        *(float4*)&Bs[lb_k][lb_n] = bv;
        __syncthreads();

        #pragma unroll
        for (int kk = 0; kk < 16; kk++) {
            float4 a = *(const float4*)&As[kk][ty * 4];
            float4 b = *(const float4*)&Bs[kk][tx * 4];
            float a4[4] = {a.x, a.y, a.z, a.w};
            float b4[4] = {b.x, b.y, b.z, b.w};
            #pragma unroll
            for (int ii = 0; ii < 4; ii++)
                #pragma unroll
                for (int jj = 0; jj < 4; jj++)
                    acc[ii][jj] += a4[ii] * b4[jj];
        }
        __syncthreads();
    }

    #pragma unroll
    for (int ii = 0; ii < 4; ii++) {
        int r = bm + ty * 4 + ii;
        if (r >= M) continue;
        #pragma unroll
        for (int jj = 0; jj < 4; jj++) {
            int cidx = bn + tx * 4 + jj;
            float v = acc[ii][jj];
            if (mode == 0)
                v = fmaxf(v + bias[cidx], 0.f);
            else
                v = fmaxf(theta * v + rtheta * resid[(size_t)r * NC + cidx], 0.f);
            C[(size_t)r * NC + cidx] = v;
        }
    }
}

// ==========================================================================
// 4) Fused head: logits = h@w1 + b1 ; out = log_softmax(logits)
//    One block (128 thr) per row; 40 threads each own one class column.
// ==========================================================================
__global__ void head_kernel(const float* __restrict__ h,
                            const float* __restrict__ w1,
                            const float* __restrict__ b1,
                            float* __restrict__ out) {
    int i = blockIdx.x, tid = threadIdx.x;
    __shared__ float sh[NHID];
    __shared__ float slog[NCLASS];
    __shared__ float s_norm;

    for (int k = tid; k < NHID; k += 128)
        sh[k] = h[(size_t)i * NHID + k];
    __syncthreads();

    if (tid < NCLASS) {
        float acc = b1[tid];
        #pragma unroll 8
        for (int k = 0; k < NHID; k++)
            acc += sh[k] * __ldg(&w1[k * NCLASS + tid]);
        slog[tid] = acc;
    }
    __syncthreads();

    if (tid == 0) {
        float m = -1e30f;
        for (int c = 0; c < NCLASS; c++) m = fmaxf(m, slog[c]);
        float s = 0.f;
        for (int c = 0; c < NCLASS; c++) s += expf(slog[c] - m);
        s_norm = m + logf(s);
    }
    __syncthreads();

    if (tid < NCLASS)
        out[(size_t)i * NCLASS + tid] = slog[tid] - s_norm;
}

// ==========================================================================
// host driver
// ==========================================================================
extern "C" void kernel_launch(void* const* d_in, const int* in_sizes, int n_in,
                              void* d_out, int out_size) {
    const float* x      = (const float*)d_in[0];  // [N, NFEAT]
    const float* adj    = (const float*)d_in[1];  // [N, N]
    const float* w0     = (const float*)d_in[2];  // [NFEAT, NHID]
    const float* b0     = (const float*)d_in[3];  // [NHID]
    const float* conv_w = (const float*)d_in[4];  // [NLAYERS, NHID, NHID]
    const float* w1     = (const float*)d_in[5];  // [NHID, NCLASS]
    const float* b1     = (const float*)d_in[6];  // [NCLASS]
    float* out = (float*)d_out;                   // [N, NCLASS]

    float *p_h0, *p_h, *p_support;
    cudaGetSymbolAddress((void**)&p_h0, g_h0);
    cudaGetSymbolAddress((void**)&p_h, g_h);
    cudaGetSymbolAddress((void**)&p_support, g_support);

    // 1) adjacency -> ELL + dinv
    build_ell_kernel<<<N, 256>>>(adj);

    // 2) h0 = relu(x @ w0 + b0)
    dim3 g0((N + 63) / 64, NHID / 64);
    gemm_epi_kernel<<<g0, 256>>>(x, w0, p_h0, N, NFEAT, NHID,
                                 b0, nullptr, 0.f, 0.f, 0);

    // 3) 8 GCNII layers
    const float* hcur = p_h0;
    for (int l = 0; l < NLAYERS; l++) {
        float theta = logf(0.5f / (float)(l + 1) + 1.0f);
        float rtheta = 1.0f - theta;
        spmm_support_kernel<<<N, NHID>>>(hcur, p_support);
        gemm_epi_kernel<<<g0, 256>>>(p_support, conv_w + (size_t)l * NHID * NHID,
                                     p_h, N, NHID, NHID,
                                     nullptr, p_support, theta, rtheta, 1);
        hcur = p_h;
    }

    // 4) logits + log_softmax
    head_kernel<<<N, 128>>>(p_h, w1, b1, out);
}

// round 3
// speedup vs baseline: 1.6444x; 1.6444x over previous
#include <cuda_runtime.h>
#include <cuda_fp16.h>
#include <math.h>
#include <stdint.h>

#define N       10000
#define NFEAT   512
#define NHID    256
#define NCLASS  40
#define NLAYERS 8
#define MAXW    128

// ---------------- device scratch (no allocation allowed) ----------------
__device__ float g_dinv[N];
__device__ int   g_rowlen[N];
__device__ int   g_cols[(size_t)N * MAXW];
__device__ float g_h0[(size_t)N * NHID];
__device__ float g_h[(size_t)N * NHID];
__device__ float g_support[(size_t)N * NHID];
__device__ __align__(16) __half g_x16[(size_t)N * NFEAT];     // fp16 copy of x
__device__ __align__(16) __half g_sup16[(size_t)N * NHID];    // fp16 copy of support
// pre-swizzled fp16 B images (W^T): per ntile, K/32 blocks of 4096 halves (8KB)
__device__ __align__(16) __half g_Bimg[(size_t)NLAYERS * NHID * NHID];
__device__ __align__(16) __half g_B0img[(size_t)NFEAT * NHID];

__device__ __forceinline__ uint32_t smem_u32(const void* p) {
    uint32_t a;
    asm("{ .reg .u64 t; cvta.to.shared.u64 t, %1; cvt.u32.u64 %0, t; }" : "=r"(a) : "l"(p));
    return a;
}
__device__ __host__ __forceinline__ uint32_t swz(uint32_t off) {
    return off ^ ((off >> 3) & 0x70);
}

// ==========================================================================
// prep kernels
// ==========================================================================
__global__ void prep_x_kernel(const float* __restrict__ x) {
    int i = blockIdx.x * 256 + threadIdx.x;
    if (i < N * NFEAT) g_x16[i] = __float2half_rn(x[i]);
}
// conv_w [l][k][n] -> per (l, ntile, kchunk) 8KB swizzled [n128][k32] block
__global__ void prep_w_kernel(const float* __restrict__ conv_w) {
    int f = blockIdx.x * 256 + threadIdx.x;
    if (f >= NLAYERS * NHID * NHID) return;
    int n = f & 255, k = (f >> 8) & 255, l = f >> 16;
    int ntile = n >> 7, nl = n & 127, kc = k >> 5, kk = k & 31;
    char* blk = (char*)(g_Bimg + (size_t)l * 65536) +
                ((size_t)(ntile * 8 + kc)) * 8192;
    *(__half*)(blk + swz(nl * 64 + kk * 2)) = __float2half_rn(conv_w[f]);
}
__global__ void prep_w0_kernel(const float* __restrict__ w0) {
    int f = blockIdx.x * 256 + threadIdx.x;
    if (f >= NFEAT * NHID) return;
    int n = f & 255, k = f >> 8;   // k in 0..511
    int ntile = n >> 7, nl = n & 127, kc = k >> 5, kk = k & 31;
    char* blk = (char*)g_B0img + ((size_t)(ntile * 16 + kc)) * 8192;
    *(__half*)(blk + swz(nl * 64 + kk * 2)) = __float2half_rn(w0[f]);
}

// ==========================================================================
// HMMA fp16 GEMM: block 128x128, BK=32, 8 warps (4m x 2n), warp tile 32x64.
//   A: fp16 row-major [M][K] global. B: pre-swizzled image blocks.
//   mode 0: C = relu(acc + bias[n]);  mode 1: C = relu(theta*acc + rtheta*resid)
// ==========================================================================
#define CP_ASYNC16(dst, src, sz) \
    asm volatile("cp.async.cg.shared.global [%0], [%1], 16, %2;" \
                 :: "r"(dst), "l"(src), "r"(sz))
#define CP_COMMIT() asm volatile("cp.async.commit_group;")
#define CP_WAIT1()  asm volatile("cp.async.wait_group 1;")

__global__ __launch_bounds__(256, 2)
void gemm_hmma_kernel(const __half* __restrict__ A, int M, int K,
                      const __half* __restrict__ Bimg,
                      float* __restrict__ C,
                      const float* __restrict__ bias,
                      const float* __restrict__ resid,
                      float theta, float rtheta, int mode) {
    __shared__ __align__(128) __half sA[2][128 * 32];
    __shared__ __align__(128) __half sB[2][128 * 32];
    int tid = threadIdx.x, lane = tid & 31, wid = tid >> 5;
    int wm = wid & 3, wn = wid >> 2;
    int bm = blockIdx.x * 128;
    int nc0 = blockIdx.y * 128;
    const __half* Bsrc = Bimg + (size_t)blockIdx.y * (K >> 5) * 4096;
    int nch = K >> 5;

    uint32_t sAb = smem_u32(sA), sBb = smem_u32(sB);

    float acc[2][8][4];
    #pragma unroll
    for (int i = 0; i < 2; i++)
        #pragma unroll
        for (int j = 0; j < 8; j++)
            #pragma unroll
            for (int r = 0; r < 4; r++) acc[i][j][r] = 0.f;

    // per-lane ldmatrix row bases (byte offsets, pre-swizzle)
    int rowA = wm * 32 + (lane & 15);
    int colA = (lane >> 4) * 16;                 // 0 or 16 bytes
    int rowB = wn * 64 + (lane & 7) + ((lane & 16) ? 8 : 0);
    int colB = ((lane >> 3) & 1) * 16;

    // ---- staging lambda-ish macros ----
    #define STAGE(c, buf) do { \
        int _c = (c), _b = (buf); \
        for (int t = tid; t < 512; t += 256) { \
            int row = t >> 2, j = t & 3; \
            uint32_t dst = sAb + _b * 8192 + swz(row * 64 + j * 16); \
            int gr = bm + row; \
            const __half* src = A + (size_t)(gr < M ? gr : 0) * K + _c * 32 + j * 8; \
            CP_ASYNC16(dst, src, (gr < M) ? 16 : 0); \
        } \
        for (int t = tid; t < 512; t += 256) { \
            uint32_t dst = sBb + _b * 8192 + t * 16; \
            const __half* src = Bsrc + (size_t)_c * 4096 + t * 8; \
            CP_ASYNC16(dst, src, 16); \
        } \
    } while (0)

    STAGE(0, 0);
    CP_COMMIT();

    for (int c = 0; c < nch; c++) {
        if (c + 1 < nch) STAGE(c + 1, (c + 1) & 1);
        CP_COMMIT();
        CP_WAIT1();
        __syncthreads();

        uint32_t aB = sAb + (c & 1) * 8192;
        uint32_t bB = sBb + (c & 1) * 8192;
        #pragma unroll
        for (int s = 0; s < 2; s++) {
            uint32_t a[2][4];
            uint32_t b[8][2];
            #pragma unroll
            for (int mm = 0; mm < 2; mm++) {
                uint32_t addr = aB + swz((rowA + mm * 16) * 64 + s * 32 + colA);
                asm volatile("ldmatrix.sync.aligned.m8n8.x4.shared.b16 {%0,%1,%2,%3}, [%4];"
                    : "=r"(a[mm][0]), "=r"(a[mm][1]), "=r"(a[mm][2]), "=r"(a[mm][3])
                    : "r"(addr));
            }
            #pragma unroll
            for (int p = 0; p < 4; p++) {
                uint32_t addr = bB + swz((rowB + p * 16) * 64 + s * 32 + colB);
                asm volatile("ldmatrix.sync.aligned.m8n8.x4.shared.b16 {%0,%1,%2,%3}, [%4];"
                    : "=r"(b[2 * p][0]), "=r"(b[2 * p][1]),
                      "=r"(b[2 * p + 1][0]), "=r"(b[2 * p + 1][1])
                    : "r"(addr));
            }
            #pragma unroll
            for (int mm = 0; mm < 2; mm++)
                #pragma unroll
                for (int nf = 0; nf < 8; nf++)
                    asm volatile(
                        "mma.sync.aligned.m16n8k16.row.col.f32.f16.f16.f32 "
                        "{%0,%1,%2,%3}, {%4,%5,%6,%7}, {%8,%9}, {%0,%1,%2,%3};"
                        : "+f"(acc[mm][nf][0]), "+f"(acc[mm][nf][1]),
                          "+f"(acc[mm][nf][2]), "+f"(acc[mm][nf][3])
                        : "r"(a[mm][0]), "r"(a[mm][1]), "r"(a[mm][2]), "r"(a[mm][3]),
                          "r"(b[nf][0]), "r"(b[nf][1]));
        }
        __syncthreads();
    }

    // ---- epilogue ----
    int quad = lane >> 2, tq = lane & 3;
    #pragma unroll
    for (int mm = 0; mm < 2; mm++) {
        #pragma unroll
        for (int half = 0; half < 2; half++) {
            int grow = bm + wm * 32 + mm * 16 + quad + half * 8;
            if (grow >= M) continue;
            #pragma unroll
            for (int nf = 0; nf < 8; nf++) {
                int nc = nc0 + wn * 64 + nf * 8 + tq * 2;
                float v0 = acc[mm][nf][half * 2 + 0];
                float v1 = acc[mm][nf][half * 2 + 1];
                float o0, o1;
                if (mode == 0) {
                    o0 = fmaxf(v0 + bias[nc], 0.f);
                    o1 = fmaxf(v1 + bias[nc + 1], 0.f);
                } else {
                    const float2 r = *(const float2*)(resid + (size_t)grow * NHID + nc);
                    o0 = fmaxf(theta * v0 + rtheta * r.x, 0.f);
                    o1 = fmaxf(theta * v1 + rtheta * r.y, 0.f);
                }
                *(float2*)(C + (size_t)grow * NHID + nc) = make_float2(o0, o1);
            }
        }
    }
}

// ==========================================================================
// ELL build (unchanged)
// ==========================================================================
__global__ void build_ell_kernel(const float* __restrict__ adj) {
    int i = blockIdx.x;
    const float* row = adj + (size_t)i * N;
    int tid = threadIdx.x, lane = tid & 31, wid = tid >> 5;
    __shared__ int s_wcnt[8];
    __shared__ int s_base;
    if (tid == 0) s_base = 0;
    __syncthreads();
    int rowoff = i * MAXW;

    for (int c0 = 0; c0 < N; c0 += 1024) {
        int c = c0 + tid * 4;
        float4 v = make_float4(0.f, 0.f, 0.f, 0.f);
        if (c + 3 < N) v = *(const float4*)(row + c);
        int p0 = (v.x != 0.f), p1 = (v.y != 0.f), p2 = (v.z != 0.f), p3 = (v.w != 0.f);
        int pcnt = p0 + p1 + p2 + p3;
        int x = pcnt;
        #pragma unroll
        for (int d = 1; d < 32; d <<= 1) {
            int y = __shfl_up_sync(0xffffffffu, x, d);
            if (lane >= d) x += y;
        }
        if (lane == 31) s_wcnt[wid] = x;
        __syncthreads();
        int wpre = 0, total = 0;
        #pragma unroll
        for (int w = 0; w < 8; w++) {
            int t = s_wcnt[w];
            if (w < wid) wpre += t;
            total += t;
        }
        int pos = s_base + wpre + (x - pcnt);
        if (p0) { if (pos < MAXW - 1) g_cols[rowoff + pos] = c + 0; pos++; }
        if (p1) { if (pos < MAXW - 1) g_cols[rowoff + pos] = c + 1; pos++; }
        if (p2) { if (pos < MAXW - 1) g_cols[rowoff + pos] = c + 2; pos++; }
        if (p3) { if (pos < MAXW - 1) g_cols[rowoff + pos] = c + 3; pos++; }
        __syncthreads();
        if (tid == 0) s_base += total;
        __syncthreads();
    }
    if (tid == 0) {
        int cnt = s_base;
        if (cnt > MAXW - 1) cnt = MAXW - 1;
        g_cols[rowoff + cnt] = i;
        g_rowlen[i] = cnt + 1;
        g_dinv[i] = rsqrtf((float)(cnt + 1));
    }
}

// ==========================================================================
// SpMM + residual mix; also emits fp16 copy of support for the GEMM A operand
// ==========================================================================
__global__ void spmm_support_kernel(const float* __restrict__ h,
                                    float* __restrict__ support,
                                    __half* __restrict__ sup16) {
    int i = blockIdx.x, tid = threadIdx.x;
    __shared__ float s_w[MAXW];
    __shared__ int   s_c[MAXW];
    int len = g_rowlen[i];
    if (tid < MAXW && tid < len) {
        int c = g_cols[i * MAXW + tid];
        s_c[tid] = c * NHID;
        s_w[tid] = g_dinv[c];
    }
    __syncthreads();
    float acc = 0.f;
    #pragma unroll 4
    for (int k = 0; k < len; k++)
        acc += s_w[k] * __ldg(&h[s_c[k] + tid]);
    float v = 0.9f * g_dinv[i] * acc + 0.1f * g_h0[(size_t)i * NHID + tid];
    support[(size_t)i * NHID + tid] = v;
    sup16[(size_t)i * NHID + tid] = __float2half_rn(v);
}

// ==========================================================================
// head: logits + log_softmax (unchanged)
// ==========================================================================
__global__ void head_kernel(const float* __restrict__ h,
                            const float* __restrict__ w1,
                            const float* __restrict__ b1,
                            float* __restrict__ out) {
    int i = blockIdx.x, tid = threadIdx.x;
    __shared__ float sh[NHID];
    __shared__ float slog[NCLASS];
    __shared__ float s_norm;
    for (int k = tid; k < NHID; k += 128)
        sh[k] = h[(size_t)i * NHID + k];
    __syncthreads();
    if (tid < NCLASS) {
        float acc = b1[tid];
        #pragma unroll 8
        for (int k = 0; k < NHID; k++)
            acc += sh[k] * __ldg(&w1[k * NCLASS + tid]);
        slog[tid] = acc;
    }
    __syncthreads();
    if (tid == 0) {
        float m = -1e30f;
        for (int c = 0; c < NCLASS; c++) m = fmaxf(m, slog[c]);
        float s = 0.f;
        for (int c = 0; c < NCLASS; c++) s += expf(slog[c] - m);
        s_norm = m + logf(s);
    }
    __syncthreads();
    if (tid < NCLASS)
        out[(size_t)i * NCLASS + tid] = slog[tid] - s_norm;
}

// ==========================================================================
// host driver
// ==========================================================================
extern "C" void kernel_launch(void* const* d_in, const int* in_sizes, int n_in,
                              void* d_out, int out_size) {
    const float* x      = (const float*)d_in[0];
    const float* adj    = (const float*)d_in[1];
    const float* w0     = (const float*)d_in[2];
    const float* b0     = (const float*)d_in[3];
    const float* conv_w = (const float*)d_in[4];
    const float* w1     = (const float*)d_in[5];
    const float* b1     = (const float*)d_in[6];
    float* out = (float*)d_out;

    float *p_h0, *p_h, *p_support;
    __half *p_Bimg, *p_B0img, *p_x16, *p_sup16;
    cudaGetSymbolAddress((void**)&p_h0, g_h0);
    cudaGetSymbolAddress((void**)&p_h, g_h);
    cudaGetSymbolAddress((void**)&p_support, g_support);
    cudaGetSymbolAddress((void**)&p_Bimg, g_Bimg);
    cudaGetSymbolAddress((void**)&p_B0img, g_B0img);
    cudaGetSymbolAddress((void**)&p_x16, g_x16);
    cudaGetSymbolAddress((void**)&p_sup16, g_sup16);

    // prep
    prep_x_kernel<<<(N * NFEAT + 255) / 256, 256>>>(x);
    prep_w_kernel<<<(NLAYERS * NHID * NHID + 255) / 256, 256>>>(conv_w);
    prep_w0_kernel<<<(NFEAT * NHID + 255) / 256, 256>>>(w0);
    build_ell_kernel<<<N, 256>>>(adj);

    dim3 gg((N + 127) / 128, 2);

    // h0 = relu(x @ w0 + b0)
    gemm_hmma_kernel<<<gg, 256>>>(p_x16, N, NFEAT, p_B0img, p_h0,
                                  b0, nullptr, 0.f, 0.f, 0);

    const float* hcur = p_h0;
    for (int l = 0; l < NLAYERS; l++) {
        float theta = logf(0.5f / (float)(l + 1) + 1.0f);
        float rtheta = 1.0f - theta;
        spmm_support_kernel<<<N, NHID>>>(hcur, p_support, p_sup16);
        gemm_hmma_kernel<<<gg, 256>>>(p_sup16, N, NHID,
                                      p_Bimg + (size_t)l * 65536, p_h,
                                      nullptr, p_support, theta, rtheta, 1);
        hcur = p_h;
    }

    head_kernel<<<N, 128>>>(p_h, w1, b1, out);
}

// round 4
// speedup vs baseline: 1.9009x; 1.1560x over previous
#include <cuda_runtime.h>
#include <cuda_fp16.h>
#include <math.h>
#include <stdint.h>

#define N       10000
#define NFEAT   512
#define NHID    256
#define NCLASS  40
#define NLAYERS 8
#define MAXW    128
#define WSEG    164   // per-warp staging capacity in build_ell

// ---------------- device scratch (no allocation allowed) ----------------
__device__ float g_dinv[N];
__device__ int   g_rowlen[N];
__device__ int   g_cols[(size_t)N * MAXW];
__device__ float g_h0[(size_t)N * NHID];
__device__ float g_h[(size_t)N * NHID];
__device__ float g_support[(size_t)N * NHID];
__device__ __align__(16) __half g_x16[(size_t)N * NFEAT];
__device__ __align__(16) __half g_h0_16[(size_t)N * NHID];
__device__ __align__(16) __half g_h16[(size_t)N * NHID];
__device__ __align__(16) __half g_sup16[(size_t)N * NHID];
__device__ __align__(16) __half g_Bimg[(size_t)NLAYERS * NHID * NHID];
__device__ __align__(16) __half g_B0img[(size_t)NFEAT * NHID];

__device__ __forceinline__ uint32_t smem_u32(const void* p) {
    uint32_t a;
    asm("{ .reg .u64 t; cvta.to.shared.u64 t, %1; cvt.u32.u64 %0, t; }" : "=r"(a) : "l"(p));
    return a;
}
__device__ __host__ __forceinline__ uint32_t swz(uint32_t off) {
    return off ^ ((off >> 3) & 0x70);
}

// ==========================================================================
// prep kernels
// ==========================================================================
__global__ void prep_x_kernel(const float* __restrict__ x) {
    int i = blockIdx.x * 256 + threadIdx.x;
    if (i < N * NFEAT) g_x16[i] = __float2half_rn(x[i]);
}
__global__ void prep_w_kernel(const float* __restrict__ conv_w) {
    int f = blockIdx.x * 256 + threadIdx.x;
    if (f >= NLAYERS * NHID * NHID) return;
    int n = f & 255, k = (f >> 8) & 255, l = f >> 16;
    int ntile = n >> 7, nl = n & 127, kc = k >> 5, kk = k & 31;
    char* blk = (char*)(g_Bimg + (size_t)l * 65536) + ((size_t)(ntile * 8 + kc)) * 8192;
    *(__half*)(blk + swz(nl * 64 + kk * 2)) = __float2half_rn(conv_w[f]);
}
__global__ void prep_w0_kernel(const float* __restrict__ w0) {
    int f = blockIdx.x * 256 + threadIdx.x;
    if (f >= NFEAT * NHID) return;
    int n = f & 255, k = f >> 8;
    int ntile = n >> 7, nl = n & 127, kc = k >> 5, kk = k & 31;
    char* blk = (char*)g_B0img + ((size_t)(ntile * 16 + kc)) * 8192;
    *(__half*)(blk + swz(nl * 64 + kk * 2)) = __float2half_rn(w0[f]);
}

// ==========================================================================
// build_ell v2: warp-private ballot/popc compaction, no hot-loop syncs.
// warp w handles chunks (w, w+8, ...), each chunk = 128 columns.
// ==========================================================================
__global__ __launch_bounds__(256)
void build_ell_kernel(const float* __restrict__ adj) {
    int i = blockIdx.x;
    const float* row = adj + (size_t)i * N;
    int tid = threadIdx.x, lane = tid & 31, w = tid >> 5;
    __shared__ int s_idx[8][WSEG];
    __shared__ int s_cnt[8];
    __shared__ int s_off[8];
    unsigned lt = (1u << lane) - 1u;
    int base = 0;

    #pragma unroll 2
    for (int chunk = w; chunk < 79; chunk += 8) {
        int c = chunk * 128 + lane * 4;
        float4 v = make_float4(0.f, 0.f, 0.f, 0.f);
        if (c + 3 < N) {
            v = *(const float4*)(row + c);
        } else {
            if (c + 0 < N) v.x = row[c + 0];
            if (c + 1 < N) v.y = row[c + 1];
            if (c + 2 < N) v.z = row[c + 2];
            if (c + 3 < N) v.w = row[c + 3];
        }
        unsigned b0 = __ballot_sync(0xffffffffu, v.x != 0.f);
        unsigned b1 = __ballot_sync(0xffffffffu, v.y != 0.f);
        unsigned b2 = __ballot_sync(0xffffffffu, v.z != 0.f);
        unsigned b3 = __ballot_sync(0xffffffffu, v.w != 0.f);
        if (b0 | b1 | b2 | b3) {
            int o1 = base + __popc(b0);
            int o2 = o1 + __popc(b1);
            int o3 = o2 + __popc(b2);
            int p;
            p = base + __popc(b0 & lt);
            if ((v.x != 0.f) && p < WSEG) s_idx[w][p] = c;
            p = o1 + __popc(b1 & lt);
            if ((v.y != 0.f) && p < WSEG) s_idx[w][p] = c + 1;
            p = o2 + __popc(b2 & lt);
            if ((v.z != 0.f) && p < WSEG) s_idx[w][p] = c + 2;
            p = o3 + __popc(b3 & lt);
            if ((v.w != 0.f) && p < WSEG) s_idx[w][p] = c + 3;
            base = o3 + __popc(b3);
        }
    }
    if (lane == 0) s_cnt[w] = base < WSEG ? base : WSEG;
    __syncthreads();
    if (tid == 0) {
        int o = 0;
        #pragma unroll
        for (int j = 0; j < 8; j++) { s_off[j] = o; o += s_cnt[j]; }
    }
    __syncthreads();
    int rowoff = i * MAXW;
    int cw = s_cnt[w];
    // per-warp nnz is tiny (avg ~4); one lane-pass suffices, guarded anyway
    for (int t = lane; t < cw; t += 32) {
        int pos = s_off[w] + t;
        if (pos < MAXW - 1) g_cols[rowoff + pos] = s_idx[w][t];
    }
    if (tid == 0) {
        int total = s_off[7] + s_cnt[7];
        if (total > MAXW - 1) total = MAXW - 1;
        g_cols[rowoff + total] = i;     // self loop last
        g_rowlen[i] = total + 1;
        g_dinv[i] = rsqrtf((float)(total + 1));
    }
}

// ==========================================================================
// HMMA fp16 GEMM (as round 3) + fp16 output image in epilogue
// ==========================================================================
#define CP_ASYNC16(dst, src, sz) \
    asm volatile("cp.async.cg.shared.global [%0], [%1], 16, %2;" \
                 :: "r"(dst), "l"(src), "r"(sz))
#define CP_COMMIT() asm volatile("cp.async.commit_group;")
#define CP_WAIT1()  asm volatile("cp.async.wait_group 1;")

__global__ __launch_bounds__(256, 2)
void gemm_hmma_kernel(const __half* __restrict__ A, int M, int K,
                      const __half* __restrict__ Bimg,
                      float* __restrict__ C,
                      __half* __restrict__ C16,
                      const float* __restrict__ bias,
                      const float* __restrict__ resid,
                      float theta, float rtheta, int mode) {
    __shared__ __align__(128) __half sA[2][128 * 32];
    __shared__ __align__(128) __half sB[2][128 * 32];
    int tid = threadIdx.x, lane = tid & 31, wid = tid >> 5;
    int wm = wid & 3, wn = wid >> 2;
    int bm = blockIdx.x * 128;
    int nc0 = blockIdx.y * 128;
    const __half* Bsrc = Bimg + (size_t)blockIdx.y * (K >> 5) * 4096;
    int nch = K >> 5;

    uint32_t sAb = smem_u32(sA), sBb = smem_u32(sB);

    float acc[2][8][4];
    #pragma unroll
    for (int i = 0; i < 2; i++)
        #pragma unroll
        for (int j = 0; j < 8; j++)
            #pragma unroll
            for (int r = 0; r < 4; r++) acc[i][j][r] = 0.f;

    int rowA = wm * 32 + (lane & 15);
    int colA = (lane >> 4) * 16;
    int rowB = wn * 64 + (lane & 7) + ((lane & 16) ? 8 : 0);
    int colB = ((lane >> 3) & 1) * 16;

    #define STAGE(c, buf) do { \
        int _c = (c), _b = (buf); \
        for (int t = tid; t < 512; t += 256) { \
            int row = t >> 2, j = t & 3; \
            uint32_t dst = sAb + _b * 8192 + swz(row * 64 + j * 16); \
            int gr = bm + row; \
            const __half* src = A + (size_t)(gr < M ? gr : 0) * K + _c * 32 + j * 8; \
            CP_ASYNC16(dst, src, (gr < M) ? 16 : 0); \
        } \
        for (int t = tid; t < 512; t += 256) { \
            uint32_t dst = sBb + _b * 8192 + t * 16; \
            const __half* src = Bsrc + (size_t)_c * 4096 + t * 8; \
            CP_ASYNC16(dst, src, 16); \
        } \
    } while (0)

    STAGE(0, 0);
    CP_COMMIT();

    for (int c = 0; c < nch; c++) {
        if (c + 1 < nch) STAGE(c + 1, (c + 1) & 1);
        CP_COMMIT();
        CP_WAIT1();
        __syncthreads();

        uint32_t aB = sAb + (c & 1) * 8192;
        uint32_t bB = sBb + (c & 1) * 8192;
        #pragma unroll
        for (int s = 0; s < 2; s++) {
            uint32_t a[2][4];
            uint32_t b[8][2];
            #pragma unroll
            for (int mm = 0; mm < 2; mm++) {
                uint32_t addr = aB + swz((rowA + mm * 16) * 64 + s * 32 + colA);
                asm volatile("ldmatrix.sync.aligned.m8n8.x4.shared.b16 {%0,%1,%2,%3}, [%4];"
                    : "=r"(a[mm][0]), "=r"(a[mm][1]), "=r"(a[mm][2]), "=r"(a[mm][3])
                    : "r"(addr));
            }
            #pragma unroll
            for (int p = 0; p < 4; p++) {
                uint32_t addr = bB + swz((rowB + p * 16) * 64 + s * 32 + colB);
                asm volatile("ldmatrix.sync.aligned.m8n8.x4.shared.b16 {%0,%1,%2,%3}, [%4];"
                    : "=r"(b[2 * p][0]), "=r"(b[2 * p][1]),
                      "=r"(b[2 * p + 1][0]), "=r"(b[2 * p + 1][1])
                    : "r"(addr));
            }
            #pragma unroll
            for (int mm = 0; mm < 2; mm++)
                #pragma unroll
                for (int nf = 0; nf < 8; nf++)
                    asm volatile(
                        "mma.sync.aligned.m16n8k16.row.col.f32.f16.f16.f32 "
                        "{%0,%1,%2,%3}, {%4,%5,%6,%7}, {%8,%9}, {%0,%1,%2,%3};"
                        : "+f"(acc[mm][nf][0]), "+f"(acc[mm][nf][1]),
                          "+f"(acc[mm][nf][2]), "+f"(acc[mm][nf][3])
                        : "r"(a[mm][0]), "r"(a[mm][1]), "r"(a[mm][2]), "r"(a[mm][3]),
                          "r"(b[nf][0]), "r"(b[nf][1]));
        }
        __syncthreads();
    }

    int quad = lane >> 2, tq = lane & 3;
    #pragma unroll
    for (int mm = 0; mm < 2; mm++) {
        #pragma unroll
        for (int half = 0; half < 2; half++) {
            int grow = bm + wm * 32 + mm * 16 + quad + half * 8;
            if (grow >= M) continue;
            #pragma unroll
            for (int nf = 0; nf < 8; nf++) {
                int nc = nc0 + wn * 64 + nf * 8 + tq * 2;
                float v0 = acc[mm][nf][half * 2 + 0];
                float v1 = acc[mm][nf][half * 2 + 1];
                float o0, o1;
                if (mode == 0) {
                    o0 = fmaxf(v0 + bias[nc], 0.f);
                    o1 = fmaxf(v1 + bias[nc + 1], 0.f);
                } else {
                    const float2 r = *(const float2*)(resid + (size_t)grow * NHID + nc);
                    o0 = fmaxf(theta * v0 + rtheta * r.x, 0.f);
                    o1 = fmaxf(theta * v1 + rtheta * r.y, 0.f);
                }
                *(float2*)(C + (size_t)grow * NHID + nc) = make_float2(o0, o1);
                *(__half2*)(C16 + (size_t)grow * NHID + nc) = __floats2half2_rn(o0, o1);
            }
        }
    }
}

// ==========================================================================
// SpMM v2: fp16 half2 gathers, 128 threads (2 features each)
// ==========================================================================
__global__ __launch_bounds__(128)
void spmm_support_kernel(const __half2* __restrict__ h2,
                         const __half2* __restrict__ h02,
                         float* __restrict__ support,
                         __half2* __restrict__ sup2) {
    int i = blockIdx.x, tid = threadIdx.x;
    __shared__ float s_w[MAXW];
    __shared__ int   s_c[MAXW];
    int len = g_rowlen[i];
    if (tid < len) {
        int c = g_cols[i * MAXW + tid];
        s_c[tid] = c * (NHID / 2);
        s_w[tid] = g_dinv[c];
    }
    __syncthreads();
    float ax = 0.f, ay = 0.f;
    #pragma unroll 4
    for (int k = 0; k < len; k++) {
        float2 f = __half22float2(__ldg(&h2[s_c[k] + tid]));
        float wv = s_w[k];
        ax += wv * f.x;
        ay += wv * f.y;
    }
    float di = 0.9f * g_dinv[i];
    float2 r0 = __half22float2(h02[i * (NHID / 2) + tid]);
    float ox = di * ax + 0.1f * r0.x;
    float oy = di * ay + 0.1f * r0.y;
    *(float2*)(support + (size_t)i * NHID + 2 * tid) = make_float2(ox, oy);
    sup2[i * (NHID / 2) + tid] = __floats2half2_rn(ox, oy);
}

// ==========================================================================
// head v2: 64 rows/block, 128 threads; thread = 8 cgroups x 16 rowgroups,
// owns 4 rows x 5 classes; float4 over k; w1 transposed in smem (pad 260).
// ==========================================================================
#define HPAD 260
#define HROWS 64
__global__ __launch_bounds__(128)
void head_kernel(const float* __restrict__ h,
                 const float* __restrict__ w1,
                 const float* __restrict__ b1,
                 float* __restrict__ out) {
    extern __shared__ float sm[];
    float* w1t = sm;                       // [40][HPAD]
    float* hs  = sm + NCLASS * HPAD;       // [64][HPAD]
    float* slog = hs + HROWS * HPAD;       // [64][40]

    int tid = threadIdx.x;
    int row0 = blockIdx.x * HROWS;

    // stage w1 transposed (coalesced read, scattered smem write)
    for (int t = tid; t < NHID * NCLASS; t += 128) {
        int k = t / NCLASS, c = t % NCLASS;
        w1t[c * HPAD + k] = w1[t];
    }
    // stage 64 h rows
    for (int t = tid; t < HROWS * NHID; t += 128) {
        int r = t >> 8, k = t & 255;
        int gr = row0 + r;
        hs[r * HPAD + k] = (gr < N) ? h[(size_t)gr * NHID + k] : 0.f;
    }
    __syncthreads();

    int cg = tid & 7;        // class group: classes cg*5 .. cg*5+4
    int rg = tid >> 3;       // row group: rows rg*4 .. rg*4+3
    float acc[4][5];
    #pragma unroll
    for (int mm = 0; mm < 4; mm++)
        #pragma unroll
        for (int j = 0; j < 5; j++) acc[mm][j] = 0.f;

    for (int k0 = 0; k0 < NHID; k0 += 4) {
        float4 wv[5];
        #pragma unroll
        for (int j = 0; j < 5; j++)
            wv[j] = *(const float4*)&w1t[(cg * 5 + j) * HPAD + k0];
        #pragma unroll
        for (int mm = 0; mm < 4; mm++) {
            float4 hv = *(const float4*)&hs[(rg * 4 + mm) * HPAD + k0];
            #pragma unroll
            for (int j = 0; j < 5; j++)
                acc[mm][j] += hv.x * wv[j].x + hv.y * wv[j].y
                            + hv.z * wv[j].z + hv.w * wv[j].w;
        }
    }
    #pragma unroll
    for (int mm = 0; mm < 4; mm++)
        #pragma unroll
        for (int j = 0; j < 5; j++)
            slog[(rg * 4 + mm) * NCLASS + cg * 5 + j] = acc[mm][j] + b1[cg * 5 + j];
    __syncthreads();

    // per-row softmax-normalize: threads 0..63 each own one row
    if (tid < HROWS) {
        int gr = row0 + tid;
        if (gr < N) {
            const float* l = slog + tid * NCLASS;
            float m = -1e30f;
            #pragma unroll 8
            for (int c = 0; c < NCLASS; c++) m = fmaxf(m, l[c]);
            float s = 0.f;
            #pragma unroll 8
            for (int c = 0; c < NCLASS; c++) s += expf(l[c] - m);
            float nrm = m + logf(s);
            float* o = out + (size_t)gr * NCLASS;
            #pragma unroll 8
            for (int c = 0; c < NCLASS; c++) o[c] = l[c] - nrm;
        }
    }
}

// ==========================================================================
// host driver
// ==========================================================================
extern "C" void kernel_launch(void* const* d_in, const int* in_sizes, int n_in,
                              void* d_out, int out_size) {
    const float* x      = (const float*)d_in[0];
    const float* adj    = (const float*)d_in[1];
    const float* w0     = (const float*)d_in[2];
    const float* b0     = (const float*)d_in[3];
    const float* conv_w = (const float*)d_in[4];
    const float* w1     = (const float*)d_in[5];
    const float* b1     = (const float*)d_in[6];
    float* out = (float*)d_out;

    float *p_h0, *p_h, *p_support;
    __half *p_Bimg, *p_B0img, *p_x16, *p_h016, *p_h16, *p_sup16;
    cudaGetSymbolAddress((void**)&p_h0, g_h0);
    cudaGetSymbolAddress((void**)&p_h, g_h);
    cudaGetSymbolAddress((void**)&p_support, g_support);
    cudaGetSymbolAddress((void**)&p_Bimg, g_Bimg);
    cudaGetSymbolAddress((void**)&p_B0img, g_B0img);
    cudaGetSymbolAddress((void**)&p_x16, g_x16);
    cudaGetSymbolAddress((void**)&p_h016, g_h0_16);
    cudaGetSymbolAddress((void**)&p_h16, g_h16);
    cudaGetSymbolAddress((void**)&p_sup16, g_sup16);

    static int head_smem = (NCLASS * HPAD + HROWS * HPAD + HROWS * NCLASS) * 4;
    cudaFuncSetAttribute(head_kernel, cudaFuncAttributeMaxDynamicSharedMemorySize, head_smem);

    // prep
    prep_x_kernel<<<(N * NFEAT + 255) / 256, 256>>>(x);
    prep_w_kernel<<<(NLAYERS * NHID * NHID + 255) / 256, 256>>>(conv_w);
    prep_w0_kernel<<<(NFEAT * NHID + 255) / 256, 256>>>(w0);
    build_ell_kernel<<<N, 256>>>(adj);

    dim3 gg((N + 127) / 128, 2);

    // h0 = relu(x @ w0 + b0)  (fp32 + fp16 images)
    gemm_hmma_kernel<<<gg, 256>>>(p_x16, N, NFEAT, p_B0img, p_h0, p_h016,
                                  b0, nullptr, 0.f, 0.f, 0);

    const __half2* hcur2 = (const __half2*)p_h016;
    for (int l = 0; l < NLAYERS; l++) {
        float theta = logf(0.5f / (float)(l + 1) + 1.0f);
        float rtheta = 1.0f - theta;
        spmm_support_kernel<<<N, 128>>>(hcur2, (const __half2*)p_h016,
                                        p_support, (__half2*)p_sup16);
        gemm_hmma_kernel<<<gg, 256>>>(p_sup16, N, NHID,
                                      p_Bimg + (size_t)l * 65536, p_h, p_h16,
                                      nullptr, p_support, theta, rtheta, 1);
        hcur2 = (const __half2*)p_h16;
    }

    head_kernel<<<(N + HROWS - 1) / HROWS, 128, head_smem>>>(p_h, w1, b1, out);
}

// round 5
// speedup vs baseline: 2.1392x; 1.1254x over previous
#include <cuda_runtime.h>
#include <cuda_fp16.h>
#include <math.h>
#include <stdint.h>

#define N       10000
#define NFEAT   512
#define NHID    256
#define NCLASS  40
#define NLAYERS 8
#define MAXW    128
#define WSEG    164

// ---------------- device scratch (no allocation allowed) ----------------
__device__ float g_dinv[N];
__device__ int   g_rowlen[N];
__device__ int   g_cols[(size_t)N * MAXW];
__device__ float g_h0[(size_t)N * NHID];
__device__ float g_h[(size_t)N * NHID];
__device__ float g_support[(size_t)N * NHID];
__device__ __align__(16) __half g_x16[(size_t)N * NFEAT];
__device__ __align__(16) __half g_h0_16[(size_t)N * NHID];
__device__ __align__(16) __half g_h16[(size_t)N * NHID];
__device__ __align__(16) __half g_sup16[(size_t)N * NHID];
__device__ __align__(16) __half g_Bimg[(size_t)NLAYERS * NHID * NHID];
__device__ __align__(16) __half g_B0img[(size_t)NFEAT * NHID];

__device__ __forceinline__ uint32_t smem_u32(const void* p) {
    uint32_t a;
    asm("{ .reg .u64 t; cvta.to.shared.u64 t, %1; cvt.u32.u64 %0, t; }" : "=r"(a) : "l"(p));
    return a;
}
__device__ __host__ __forceinline__ uint32_t swz(uint32_t off) {
    return off ^ ((off >> 3) & 0x70);
}

// ==========================================================================
// prep kernels — B images now 4KB blocks [n64][k32], 4 n-tiles
// ==========================================================================
__global__ void prep_x_kernel(const float* __restrict__ x) {
    int i = blockIdx.x * 256 + threadIdx.x;
    if (i < N * NFEAT) g_x16[i] = __float2half_rn(x[i]);
}
__global__ void prep_w_kernel(const float* __restrict__ conv_w) {
    int f = blockIdx.x * 256 + threadIdx.x;
    if (f >= NLAYERS * NHID * NHID) return;
    int n = f & 255, k = (f >> 8) & 255, l = f >> 16;
    int ntile = n >> 6, nl = n & 63, kc = k >> 5, kk = k & 31;
    char* blk = (char*)(g_Bimg + (size_t)l * 65536) + ((size_t)(ntile * 8 + kc)) * 4096;
    *(__half*)(blk + swz(nl * 64 + kk * 2)) = __float2half_rn(conv_w[f]);
}
__global__ void prep_w0_kernel(const float* __restrict__ w0) {
    int f = blockIdx.x * 256 + threadIdx.x;
    if (f >= NFEAT * NHID) return;
    int n = f & 255, k = f >> 8;
    int ntile = n >> 6, nl = n & 63, kc = k >> 5, kk = k & 31;
    char* blk = (char*)g_B0img + ((size_t)(ntile * 16 + kc)) * 4096;
    *(__half*)(blk + swz(nl * 64 + kk * 2)) = __float2half_rn(w0[f]);
}

// ==========================================================================
// build_ell v3: ballot/popc compaction + register prefetch + streaming loads
// ==========================================================================
__device__ __forceinline__ float4 ell_load(const float* row, int chunk, int lane) {
    int c = chunk * 128 + lane * 4;
    float4 v = make_float4(0.f, 0.f, 0.f, 0.f);
    if (c + 3 < N) {
        v = __ldcs((const float4*)(row + c));
    } else {
        if (c + 0 < N) v.x = row[c + 0];
        if (c + 1 < N) v.y = row[c + 1];
        if (c + 2 < N) v.z = row[c + 2];
        if (c + 3 < N) v.w = row[c + 3];
    }
    return v;
}

__global__ __launch_bounds__(256)
void build_ell_kernel(const float* __restrict__ adj) {
    int i = blockIdx.x;
    const float* row = adj + (size_t)i * N;
    int tid = threadIdx.x, lane = tid & 31, w = tid >> 5;
    __shared__ int s_idx[8][WSEG];
    __shared__ int s_cnt[8];
    __shared__ int s_off[8];
    unsigned lt = (1u << lane) - 1u;
    int base = 0;

    float4 cur = ell_load(row, w, lane);
    for (int chunk = w; chunk < 79; chunk += 8) {
        float4 nv = make_float4(0.f, 0.f, 0.f, 0.f);
        if (chunk + 8 < 79) nv = ell_load(row, chunk + 8, lane);
        int c = chunk * 128 + lane * 4;
        unsigned b0 = __ballot_sync(0xffffffffu, cur.x != 0.f);
        unsigned b1 = __ballot_sync(0xffffffffu, cur.y != 0.f);
        unsigned b2 = __ballot_sync(0xffffffffu, cur.z != 0.f);
        unsigned b3 = __ballot_sync(0xffffffffu, cur.w != 0.f);
        if (b0 | b1 | b2 | b3) {
            int o1 = base + __popc(b0);
            int o2 = o1 + __popc(b1);
            int o3 = o2 + __popc(b2);
            int p;
            p = base + __popc(b0 & lt);
            if ((cur.x != 0.f) && p < WSEG) s_idx[w][p] = c;
            p = o1 + __popc(b1 & lt);
            if ((cur.y != 0.f) && p < WSEG) s_idx[w][p] = c + 1;
            p = o2 + __popc(b2 & lt);
            if ((cur.z != 0.f) && p < WSEG) s_idx[w][p] = c + 2;
            p = o3 + __popc(b3 & lt);
            if ((cur.w != 0.f) && p < WSEG) s_idx[w][p] = c + 3;
            base = o3 + __popc(b3);
        }
        cur = nv;
    }
    if (lane == 0) s_cnt[w] = base < WSEG ? base : WSEG;
    __syncthreads();
    if (tid == 0) {
        int o = 0;
        #pragma unroll
        for (int j = 0; j < 8; j++) { s_off[j] = o; o += s_cnt[j]; }
    }
    __syncthreads();
    int rowoff = i * MAXW;
    int cw = s_cnt[w];
    for (int t = lane; t < cw; t += 32) {
        int pos = s_off[w] + t;
        if (pos < MAXW - 1) g_cols[rowoff + pos] = s_idx[w][t];
    }
    if (tid == 0) {
        int total = s_off[7] + s_cnt[7];
        if (total > MAXW - 1) total = MAXW - 1;
        g_cols[rowoff + total] = i;
        g_rowlen[i] = total + 1;
        g_dinv[i] = rsqrtf((float)(total + 1));
    }
}

// ==========================================================================
// HMMA fp16 GEMM v2: tile 64x64, BK=32, 128 threads, 4 warps (2m x 2n),
// warp tile 32x32. Grid ~628 CTAs -> good chip balance.
// ==========================================================================
#define CP_ASYNC16(dst, src, sz) \
    asm volatile("cp.async.cg.shared.global [%0], [%1], 16, %2;" \
                 :: "r"(dst), "l"(src), "r"(sz))
#define CP_COMMIT() asm volatile("cp.async.commit_group;")
#define CP_WAIT1()  asm volatile("cp.async.wait_group 1;")

__global__ __launch_bounds__(128, 8)
void gemm_hmma_kernel(const __half* __restrict__ A, int M, int K,
                      const __half* __restrict__ Bimg,
                      float* __restrict__ C,
                      __half* __restrict__ C16,
                      const float* __restrict__ bias,
                      const float* __restrict__ resid,
                      float theta, float rtheta, int mode) {
    __shared__ __align__(128) __half sA[2][64 * 32];
    __shared__ __align__(128) __half sB[2][64 * 32];
    int tid = threadIdx.x, lane = tid & 31, wid = tid >> 5;
    int wm = wid & 1, wn = wid >> 1;
    int bm = blockIdx.x * 64;
    int nc0 = blockIdx.y * 64;
    const __half* Bsrc = Bimg + (size_t)blockIdx.y * (K >> 5) * 2048;
    int nch = K >> 5;

    uint32_t sAb = smem_u32(sA), sBb = smem_u32(sB);

    float acc[2][4][4];
    #pragma unroll
    for (int i = 0; i < 2; i++)
        #pragma unroll
        for (int j = 0; j < 4; j++)
            #pragma unroll
            for (int r = 0; r < 4; r++) acc[i][j][r] = 0.f;

    int rowA = wm * 32 + (lane & 15);
    int colA = (lane >> 4) * 16;
    int rowB = wn * 32 + (lane & 7) + ((lane & 16) ? 8 : 0);
    int colB = ((lane >> 3) & 1) * 16;

    // stage: A 64x32 (4KB) + B 4KB, 128 threads x 2 x 16B each
    #define STAGE(c, buf) do { \
        int _c = (c), _b = (buf); \
        for (int t = tid; t < 256; t += 128) { \
            int row = t >> 2, j = t & 3; \
            uint32_t dst = sAb + _b * 4096 + swz(row * 64 + j * 16); \
            int gr = bm + row; \
            const __half* src = A + (size_t)(gr < M ? gr : 0) * K + _c * 32 + j * 8; \
            CP_ASYNC16(dst, src, (gr < M) ? 16 : 0); \
        } \
        for (int t = tid; t < 256; t += 128) { \
            uint32_t dst = sBb + _b * 4096 + t * 16; \
            const __half* src = Bsrc + (size_t)_c * 2048 + t * 8; \
            CP_ASYNC16(dst, src, 16); \
        } \
    } while (0)

    STAGE(0, 0);
    CP_COMMIT();

    for (int c = 0; c < nch; c++) {
        if (c + 1 < nch) STAGE(c + 1, (c + 1) & 1);
        CP_COMMIT();
        CP_WAIT1();
        __syncthreads();

        uint32_t aB = sAb + (c & 1) * 4096;
        uint32_t bB = sBb + (c & 1) * 4096;
        #pragma unroll
        for (int s = 0; s < 2; s++) {
            uint32_t a[2][4];
            uint32_t b[4][2];
            #pragma unroll
            for (int mm = 0; mm < 2; mm++) {
                uint32_t addr = aB + swz((rowA + mm * 16) * 64 + s * 32 + colA);
                asm volatile("ldmatrix.sync.aligned.m8n8.x4.shared.b16 {%0,%1,%2,%3}, [%4];"
                    : "=r"(a[mm][0]), "=r"(a[mm][1]), "=r"(a[mm][2]), "=r"(a[mm][3])
                    : "r"(addr));
            }
            #pragma unroll
            for (int p = 0; p < 2; p++) {
                uint32_t addr = bB + swz((rowB + p * 16) * 64 + s * 32 + colB);
                asm volatile("ldmatrix.sync.aligned.m8n8.x4.shared.b16 {%0,%1,%2,%3}, [%4];"
                    : "=r"(b[2 * p][0]), "=r"(b[2 * p][1]),
                      "=r"(b[2 * p + 1][0]), "=r"(b[2 * p + 1][1])
                    : "r"(addr));
            }
            #pragma unroll
            for (int mm = 0; mm < 2; mm++)
                #pragma unroll
                for (int nf = 0; nf < 4; nf++)
                    asm volatile(
                        "mma.sync.aligned.m16n8k16.row.col.f32.f16.f16.f32 "
                        "{%0,%1,%2,%3}, {%4,%5,%6,%7}, {%8,%9}, {%0,%1,%2,%3};"
                        : "+f"(acc[mm][nf][0]), "+f"(acc[mm][nf][1]),
                          "+f"(acc[mm][nf][2]), "+f"(acc[mm][nf][3])
                        : "r"(a[mm][0]), "r"(a[mm][1]), "r"(a[mm][2]), "r"(a[mm][3]),
                          "r"(b[nf][0]), "r"(b[nf][1]));
        }
        __syncthreads();
    }

    int quad = lane >> 2, tq = lane & 3;
    #pragma unroll
    for (int mm = 0; mm < 2; mm++) {
        #pragma unroll
        for (int half = 0; half < 2; half++) {
            int grow = bm + wm * 32 + mm * 16 + quad + half * 8;
            if (grow >= M) continue;
            #pragma unroll
            for (int nf = 0; nf < 4; nf++) {
                int nc = nc0 + wn * 32 + nf * 8 + tq * 2;
                float v0 = acc[mm][nf][half * 2 + 0];
                float v1 = acc[mm][nf][half * 2 + 1];
                float o0, o1;
                if (mode == 0) {
                    o0 = fmaxf(v0 + bias[nc], 0.f);
                    o1 = fmaxf(v1 + bias[nc + 1], 0.f);
                } else {
                    const float2 r = *(const float2*)(resid + (size_t)grow * NHID + nc);
                    o0 = fmaxf(theta * v0 + rtheta * r.x, 0.f);
                    o1 = fmaxf(theta * v1 + rtheta * r.y, 0.f);
                }
                *(float2*)(C + (size_t)grow * NHID + nc) = make_float2(o0, o1);
                *(__half2*)(C16 + (size_t)grow * NHID + nc) = __floats2half2_rn(o0, o1);
            }
        }
    }
}

// ==========================================================================
// SpMM: fp16 half2 gathers, 128 threads (2 features each)
// ==========================================================================
__global__ __launch_bounds__(128)
void spmm_support_kernel(const __half2* __restrict__ h2,
                         const __half2* __restrict__ h02,
                         float* __restrict__ support,
                         __half2* __restrict__ sup2) {
    int i = blockIdx.x, tid = threadIdx.x;
    __shared__ float s_w[MAXW];
    __shared__ int   s_c[MAXW];
    int len = g_rowlen[i];
    if (tid < len) {
        int c = g_cols[i * MAXW + tid];
        s_c[tid] = c * (NHID / 2);
        s_w[tid] = g_dinv[c];
    }
    __syncthreads();
    float ax = 0.f, ay = 0.f;
    #pragma unroll 4
    for (int k = 0; k < len; k++) {
        float2 f = __half22float2(__ldg(&h2[s_c[k] + tid]));
        float wv = s_w[k];
        ax += wv * f.x;
        ay += wv * f.y;
    }
    float di = 0.9f * g_dinv[i];
    float2 r0 = __half22float2(h02[i * (NHID / 2) + tid]);
    float ox = di * ax + 0.1f * r0.x;
    float oy = di * ay + 0.1f * r0.y;
    *(float2*)(support + (size_t)i * NHID + 2 * tid) = make_float2(ox, oy);
    sup2[i * (NHID / 2) + tid] = __floats2half2_rn(ox, oy);
}

// ==========================================================================
// head: 64 rows/block, 128 threads, register tiled 4x5
// ==========================================================================
#define HPAD 260
#define HROWS 64
__global__ __launch_bounds__(128)
void head_kernel(const float* __restrict__ h,
                 const float* __restrict__ w1,
                 const float* __restrict__ b1,
                 float* __restrict__ out) {
    extern __shared__ float sm[];
    float* w1t = sm;
    float* hs  = sm + NCLASS * HPAD;
    float* slog = hs + HROWS * HPAD;

    int tid = threadIdx.x;
    int row0 = blockIdx.x * HROWS;

    for (int t = tid; t < NHID * NCLASS; t += 128) {
        int k = t / NCLASS, c = t % NCLASS;
        w1t[c * HPAD + k] = w1[t];
    }
    for (int t = tid; t < HROWS * NHID; t += 128) {
        int r = t >> 8, k = t & 255;
        int gr = row0 + r;
        hs[r * HPAD + k] = (gr < N) ? h[(size_t)gr * NHID + k] : 0.f;
    }
    __syncthreads();

    int cg = tid & 7;
    int rg = tid >> 3;
    float acc[4][5];
    #pragma unroll
    for (int mm = 0; mm < 4; mm++)
        #pragma unroll
        for (int j = 0; j < 5; j++) acc[mm][j] = 0.f;

    for (int k0 = 0; k0 < NHID; k0 += 4) {
        float4 wv[5];
        #pragma unroll
        for (int j = 0; j < 5; j++)
            wv[j] = *(const float4*)&w1t[(cg * 5 + j) * HPAD + k0];
        #pragma unroll
        for (int mm = 0; mm < 4; mm++) {
            float4 hv = *(const float4*)&hs[(rg * 4 + mm) * HPAD + k0];
            #pragma unroll
            for (int j = 0; j < 5; j++)
                acc[mm][j] += hv.x * wv[j].x + hv.y * wv[j].y
                            + hv.z * wv[j].z + hv.w * wv[j].w;
        }
    }
    #pragma unroll
    for (int mm = 0; mm < 4; mm++)
        #pragma unroll
        for (int j = 0; j < 5; j++)
            slog[(rg * 4 + mm) * NCLASS + cg * 5 + j] = acc[mm][j] + b1[cg * 5 + j];
    __syncthreads();

    if (tid < HROWS) {
        int gr = row0 + tid;
        if (gr < N) {
            const float* l = slog + tid * NCLASS;
            float m = -1e30f;
            #pragma unroll 8
            for (int c = 0; c < NCLASS; c++) m = fmaxf(m, l[c]);
            float s = 0.f;
            #pragma unroll 8
            for (int c = 0; c < NCLASS; c++) s += expf(l[c] - m);
            float nrm = m + logf(s);
            float* o = out + (size_t)gr * NCLASS;
            #pragma unroll 8
            for (int c = 0; c < NCLASS; c++) o[c] = l[c] - nrm;
        }
    }
}

// ==========================================================================
// host driver
// ==========================================================================
extern "C" void kernel_launch(void* const* d_in, const int* in_sizes, int n_in,
                              void* d_out, int out_size) {
    const float* x      = (const float*)d_in[0];
    const float* adj    = (const float*)d_in[1];
    const float* w0     = (const float*)d_in[2];
    const float* b0     = (const float*)d_in[3];
    const float* conv_w = (const float*)d_in[4];
    const float* w1     = (const float*)d_in[5];
    const float* b1     = (const float*)d_in[6];
    float* out = (float*)d_out;

    float *p_h0, *p_h, *p_support;
    __half *p_Bimg, *p_B0img, *p_x16, *p_h016, *p_h16, *p_sup16;
    cudaGetSymbolAddress((void**)&p_h0, g_h0);
    cudaGetSymbolAddress((void**)&p_h, g_h);
    cudaGetSymbolAddress((void**)&p_support, g_support);
    cudaGetSymbolAddress((void**)&p_Bimg, g_Bimg);
    cudaGetSymbolAddress((void**)&p_B0img, g_B0img);
    cudaGetSymbolAddress((void**)&p_x16, g_x16);
    cudaGetSymbolAddress((void**)&p_h016, g_h0_16);
    cudaGetSymbolAddress((void**)&p_h16, g_h16);
    cudaGetSymbolAddress((void**)&p_sup16, g_sup16);

    static int head_smem = (NCLASS * HPAD + HROWS * HPAD + HROWS * NCLASS) * 4;
    cudaFuncSetAttribute(head_kernel, cudaFuncAttributeMaxDynamicSharedMemorySize, head_smem);

    prep_x_kernel<<<(N * NFEAT + 255) / 256, 256>>>(x);
    prep_w_kernel<<<(NLAYERS * NHID * NHID + 255) / 256, 256>>>(conv_w);
    prep_w0_kernel<<<(NFEAT * NHID + 255) / 256, 256>>>(w0);
    build_ell_kernel<<<N, 256>>>(adj);

    dim3 gg((N + 63) / 64, 4);

    gemm_hmma_kernel<<<gg, 128>>>(p_x16, N, NFEAT, p_B0img, p_h0, p_h016,
                                  b0, nullptr, 0.f, 0.f, 0);

    const __half2* hcur2 = (const __half2*)p_h016;
    for (int l = 0; l < NLAYERS; l++) {
        float theta = logf(0.5f / (float)(l + 1) + 1.0f);
        float rtheta = 1.0f - theta;
        spmm_support_kernel<<<N, 128>>>(hcur2, (const __half2*)p_h016,
                                        p_support, (__half2*)p_sup16);
        gemm_hmma_kernel<<<gg, 128>>>(p_sup16, N, NHID,
                                      p_Bimg + (size_t)l * 65536, p_h, p_h16,
                                      nullptr, p_support, theta, rtheta, 1);
        hcur2 = (const __half2*)p_h16;
    }

    head_kernel<<<(N + HROWS - 1) / HROWS, 128, head_smem>>>(p_h, w1, b1, out);
}

// round 6
// speedup vs baseline: 2.3539x; 1.1004x over previous
#include <cuda_runtime.h>
#include <cuda_fp16.h>
#include <math.h>
#include <stdint.h>

#define N       10000
#define NFEAT   512
#define NHID    256
#define NCLASS  40
#define NLAYERS 8
#define MAXW    128
#define WSEG    164

// ---------------- device scratch (no allocation allowed) ----------------
__device__ float g_dinv[N];
__device__ int   g_rowlen[N];
__device__ int   g_cols[(size_t)N * MAXW];
__device__ float g_h[(size_t)N * NHID];
__device__ float g_support[(size_t)N * NHID];
__device__ __align__(16) __half g_x16[(size_t)N * NFEAT];
__device__ __align__(16) __half g_h0_16[(size_t)N * NHID];
__device__ __align__(16) __half g_h16[(size_t)N * NHID];
__device__ __align__(16) __half g_sup16[(size_t)N * NHID];
__device__ __align__(16) __half g_Bimg[(size_t)NLAYERS * NHID * NHID];
__device__ __align__(16) __half g_B0img[(size_t)NFEAT * NHID];

__device__ __forceinline__ uint32_t smem_u32(const void* p) {
    uint32_t a;
    asm("{ .reg .u64 t; cvta.to.shared.u64 t, %1; cvt.u32.u64 %0, t; }" : "=r"(a) : "l"(p));
    return a;
}
__device__ __host__ __forceinline__ uint32_t swz(uint32_t off) {
    return off ^ ((off >> 3) & 0x70);
}

// ==========================================================================
// merged prep: x->fp16, conv_w->images, w0->images
// B images: 4KB blocks [n64][k32] (64B rows, swz), blocks consecutive in k
// ==========================================================================
__global__ void prep_all_kernel(const float* __restrict__ x,
                                const float* __restrict__ conv_w,
                                const float* __restrict__ w0) {
    int i = blockIdx.x * 256 + threadIdx.x;
    if (i < N * NFEAT) g_x16[i] = __float2half_rn(x[i]);
    if (i < NLAYERS * NHID * NHID) {
        int n = i & 255, k = (i >> 8) & 255, l = i >> 16;
        int ntile = n >> 6, nl = n & 63, kc = k >> 5, kk = k & 31;
        char* blk = (char*)(g_Bimg + (size_t)l * 65536) + ((size_t)(ntile * 8 + kc)) * 4096;
        *(__half*)(blk + swz(nl * 64 + kk * 2)) = __float2half_rn(conv_w[i]);
    }
    if (i < NFEAT * NHID) {
        int n = i & 255, k = i >> 8;
        int ntile = n >> 6, nl = n & 63, kc = k >> 5, kk = k & 31;
        char* blk = (char*)g_B0img + ((size_t)(ntile * 16 + kc)) * 4096;
        *(__half*)(blk + swz(nl * 64 + kk * 2)) = __float2half_rn(w0[i]);
    }
}

// ==========================================================================
// build_ell v4: pair-unrolled loads (MLP 2) + ballot/popc compaction
// ==========================================================================
__device__ __forceinline__ float4 ell_load(const float* row, int chunk, int lane) {
    int c = chunk * 128 + lane * 4;
    float4 v = make_float4(0.f, 0.f, 0.f, 0.f);
    if (c + 3 < N) {
        v = __ldcs((const float4*)(row + c));
    } else {
        if (c + 0 < N) v.x = row[c + 0];
        if (c + 1 < N) v.y = row[c + 1];
        if (c + 2 < N) v.z = row[c + 2];
        if (c + 3 < N) v.w = row[c + 3];
    }
    return v;
}

__global__ __launch_bounds__(256)
void build_ell_kernel(const float* __restrict__ adj) {
    int i = blockIdx.x;
    const float* row = adj + (size_t)i * N;
    int tid = threadIdx.x, lane = tid & 31, w = tid >> 5;
    __shared__ int s_idx[8][WSEG];
    __shared__ int s_cnt[8];
    __shared__ int s_off[8];
    unsigned lt = (1u << lane) - 1u;
    int base = 0;

    #define ELL_PROC(v, chunk) do { \
        int c = (chunk) * 128 + lane * 4; \
        unsigned b0 = __ballot_sync(0xffffffffu, (v).x != 0.f); \
        unsigned b1 = __ballot_sync(0xffffffffu, (v).y != 0.f); \
        unsigned b2 = __ballot_sync(0xffffffffu, (v).z != 0.f); \
        unsigned b3 = __ballot_sync(0xffffffffu, (v).w != 0.f); \
        if (b0 | b1 | b2 | b3) { \
            int o1 = base + __popc(b0); \
            int o2 = o1 + __popc(b1); \
            int o3 = o2 + __popc(b2); \
            int p; \
            p = base + __popc(b0 & lt); \
            if (((v).x != 0.f) && p < WSEG) s_idx[w][p] = c; \
            p = o1 + __popc(b1 & lt); \
            if (((v).y != 0.f) && p < WSEG) s_idx[w][p] = c + 1; \
            p = o2 + __popc(b2 & lt); \
            if (((v).z != 0.f) && p < WSEG) s_idx[w][p] = c + 2; \
            p = o3 + __popc(b3 & lt); \
            if (((v).w != 0.f) && p < WSEG) s_idx[w][p] = c + 3; \
            base = o3 + __popc(b3); \
        } \
    } while (0)

    for (int c0 = w; c0 < 79; c0 += 16) {
        float4 vA = ell_load(row, c0, lane);
        int hasB = (c0 + 8) < 79;
        float4 vB = make_float4(0.f, 0.f, 0.f, 0.f);
        if (hasB) vB = ell_load(row, c0 + 8, lane);
        ELL_PROC(vA, c0);
        if (hasB) ELL_PROC(vB, c0 + 8);
    }
    if (lane == 0) s_cnt[w] = base < WSEG ? base : WSEG;
    __syncthreads();
    if (tid == 0) {
        int o = 0;
        #pragma unroll
        for (int j = 0; j < 8; j++) { s_off[j] = o; o += s_cnt[j]; }
    }
    __syncthreads();
    int rowoff = i * MAXW;
    int cw = s_cnt[w];
    for (int t = lane; t < cw; t += 32) {
        int pos = s_off[w] + t;
        if (pos < MAXW - 1) g_cols[rowoff + pos] = s_idx[w][t];
    }
    if (tid == 0) {
        int total = s_off[7] + s_cnt[7];
        if (total > MAXW - 1) total = MAXW - 1;
        g_cols[rowoff + total] = i;
        g_rowlen[i] = total + 1;
        g_dinv[i] = rsqrtf((float)(total + 1));
    }
}

// ==========================================================================
// HMMA fp16 GEMM v3: tile 64x64, BK=64 (2 B-blocks/iter), 128 thr, 4 warps.
// A smem: 64 rows x 128B (canonical SW128). C fp32 write optional.
// ==========================================================================
#define CP_ASYNC16(dst, src, sz) \
    asm volatile("cp.async.cg.shared.global [%0], [%1], 16, %2;" \
                 :: "r"(dst), "l"(src), "r"(sz))
#define CP_COMMIT() asm volatile("cp.async.commit_group;")
#define CP_WAIT1()  asm volatile("cp.async.wait_group 1;")

__global__ __launch_bounds__(128, 6)
void gemm_hmma_kernel(const __half* __restrict__ A, int M, int K,
                      const __half* __restrict__ Bimg,
                      float* __restrict__ C,            // may be null
                      __half* __restrict__ C16,
                      const float* __restrict__ bias,
                      const float* __restrict__ resid,
                      float theta, float rtheta, int mode) {
    __shared__ __align__(128) __half sA[2][64 * 64];
    __shared__ __align__(128) __half sB[2][64 * 64];
    int tid = threadIdx.x, lane = tid & 31, wid = tid >> 5;
    int wm = wid & 1, wn = wid >> 1;
    int bm = blockIdx.x * 64;
    int nc0 = blockIdx.y * 64;
    const __half* Bsrc = Bimg + (size_t)blockIdx.y * (K >> 5) * 2048;
    int nch = K >> 6;

    uint32_t sAb = smem_u32(sA), sBb = smem_u32(sB);

    float acc[2][4][4];
    #pragma unroll
    for (int i = 0; i < 2; i++)
        #pragma unroll
        for (int j = 0; j < 4; j++)
            #pragma unroll
            for (int r = 0; r < 4; r++) acc[i][j][r] = 0.f;

    int rowA = wm * 32 + (lane & 15);
    int colA = (lane >> 4) * 16;
    int rowB = wn * 32 + (lane & 7) + ((lane & 16) ? 8 : 0);
    int colB = ((lane >> 3) & 1) * 16;

    // A: 64 rows x 64k = 8KB (128B rows); B: 2 x 4KB image blocks
    #define STAGE(c, buf) do { \
        int _c = (c), _b = (buf); \
        for (int t = tid; t < 512; t += 128) { \
            int row = t >> 3, j = t & 7; \
            uint32_t dst = sAb + _b * 8192 + swz(row * 128 + j * 16); \
            int gr = bm + row; \
            const __half* src = A + (size_t)(gr < M ? gr : 0) * K + _c * 64 + j * 8; \
            CP_ASYNC16(dst, src, (gr < M) ? 16 : 0); \
        } \
        for (int t = tid; t < 512; t += 128) { \
            uint32_t dst = sBb + _b * 8192 + t * 16; \
            const __half* src = Bsrc + (size_t)_c * 4096 + t * 8; \
            CP_ASYNC16(dst, src, 16); \
        } \
    } while (0)

    STAGE(0, 0);
    CP_COMMIT();

    for (int c = 0; c < nch; c++) {
        if (c + 1 < nch) STAGE(c + 1, (c + 1) & 1);
        CP_COMMIT();
        CP_WAIT1();
        __syncthreads();

        uint32_t aB = sAb + (c & 1) * 8192;
        uint32_t bB = sBb + (c & 1) * 8192;
        #pragma unroll
        for (int s = 0; s < 4; s++) {
            uint32_t a[2][4];
            uint32_t b[4][2];
            #pragma unroll
            for (int mm = 0; mm < 2; mm++) {
                uint32_t addr = aB + swz((rowA + mm * 16) * 128 + s * 32 + colA);
                asm volatile("ldmatrix.sync.aligned.m8n8.x4.shared.b16 {%0,%1,%2,%3}, [%4];"
                    : "=r"(a[mm][0]), "=r"(a[mm][1]), "=r"(a[mm][2]), "=r"(a[mm][3])
                    : "r"(addr));
            }
            #pragma unroll
            for (int p = 0; p < 2; p++) {
                uint32_t addr = bB + (s >> 1) * 4096
                              + swz((rowB + p * 16) * 64 + (s & 1) * 32 + colB);
                asm volatile("ldmatrix.sync.aligned.m8n8.x4.shared.b16 {%0,%1,%2,%3}, [%4];"
                    : "=r"(b[2 * p][0]), "=r"(b[2 * p][1]),
                      "=r"(b[2 * p + 1][0]), "=r"(b[2 * p + 1][1])
                    : "r"(addr));
            }
            #pragma unroll
            for (int mm = 0; mm < 2; mm++)
                #pragma unroll
                for (int nf = 0; nf < 4; nf++)
                    asm volatile(
                        "mma.sync.aligned.m16n8k16.row.col.f32.f16.f16.f32 "
                        "{%0,%1,%2,%3}, {%4,%5,%6,%7}, {%8,%9}, {%0,%1,%2,%3};"
                        : "+f"(acc[mm][nf][0]), "+f"(acc[mm][nf][1]),
                          "+f"(acc[mm][nf][2]), "+f"(acc[mm][nf][3])
                        : "r"(a[mm][0]), "r"(a[mm][1]), "r"(a[mm][2]), "r"(a[mm][3]),
                          "r"(b[nf][0]), "r"(b[nf][1]));
        }
        __syncthreads();
    }

    int quad = lane >> 2, tq = lane & 3;
    #pragma unroll
    for (int mm = 0; mm < 2; mm++) {
        #pragma unroll
        for (int half = 0; half < 2; half++) {
            int grow = bm + wm * 32 + mm * 16 + quad + half * 8;
            if (grow >= M) continue;
            #pragma unroll
            for (int nf = 0; nf < 4; nf++) {
                int nc = nc0 + wn * 32 + nf * 8 + tq * 2;
                float v0 = acc[mm][nf][half * 2 + 0];
                float v1 = acc[mm][nf][half * 2 + 1];
                float o0, o1;
                if (mode == 0) {
                    o0 = fmaxf(v0 + bias[nc], 0.f);
                    o1 = fmaxf(v1 + bias[nc + 1], 0.f);
                } else {
                    const float2 r = *(const float2*)(resid + (size_t)grow * NHID + nc);
                    o0 = fmaxf(theta * v0 + rtheta * r.x, 0.f);
                    o1 = fmaxf(theta * v1 + rtheta * r.y, 0.f);
                }
                if (C) *(float2*)(C + (size_t)grow * NHID + nc) = make_float2(o0, o1);
                *(__half2*)(C16 + (size_t)grow * NHID + nc) = __floats2half2_rn(o0, o1);
            }
        }
    }
}

// ==========================================================================
// SpMM: fp16 half2 gathers, 128 threads (2 features each)
// ==========================================================================
__global__ __launch_bounds__(128)
void spmm_support_kernel(const __half2* __restrict__ h2,
                         const __half2* __restrict__ h02,
                         float* __restrict__ support,
                         __half2* __restrict__ sup2) {
    int i = blockIdx.x, tid = threadIdx.x;
    __shared__ float s_w[MAXW];
    __shared__ int   s_c[MAXW];
    int len = g_rowlen[i];
    if (tid < len) {
        int c = g_cols[i * MAXW + tid];
        s_c[tid] = c * (NHID / 2);
        s_w[tid] = g_dinv[c];
    }
    __syncthreads();
    float ax = 0.f, ay = 0.f;
    #pragma unroll 4
    for (int k = 0; k < len; k++) {
        float2 f = __half22float2(__ldg(&h2[s_c[k] + tid]));
        float wv = s_w[k];
        ax += wv * f.x;
        ay += wv * f.y;
    }
    float di = 0.9f * g_dinv[i];
    float2 r0 = __half22float2(h02[i * (NHID / 2) + tid]);
    float ox = di * ax + 0.1f * r0.x;
    float oy = di * ay + 0.1f * r0.y;
    *(float2*)(support + (size_t)i * NHID + 2 * tid) = make_float2(ox, oy);
    sup2[i * (NHID / 2) + tid] = __floats2half2_rn(ox, oy);
}

// ==========================================================================
// head: 64 rows/block, 128 threads, register tiled 4x5
// ==========================================================================
#define HPAD 260
#define HROWS 64
__global__ __launch_bounds__(128)
void head_kernel(const float* __restrict__ h,
                 const float* __restrict__ w1,
                 const float* __restrict__ b1,
                 float* __restrict__ out) {
    extern __shared__ float sm[];
    float* w1t = sm;
    float* hs  = sm + NCLASS * HPAD;
    float* slog = hs + HROWS * HPAD;

    int tid = threadIdx.x;
    int row0 = blockIdx.x * HROWS;

    for (int t = tid; t < NHID * NCLASS; t += 128) {
        int k = t / NCLASS, c = t % NCLASS;
        w1t[c * HPAD + k] = w1[t];
    }
    for (int t = tid; t < HROWS * NHID; t += 128) {
        int r = t >> 8, k = t & 255;
        int gr = row0 + r;
        hs[r * HPAD + k] = (gr < N) ? h[(size_t)gr * NHID + k] : 0.f;
    }
    __syncthreads();

    int cg = tid & 7;
    int rg = tid >> 3;
    float acc[4][5];
    #pragma unroll
    for (int mm = 0; mm < 4; mm++)
        #pragma unroll
        for (int j = 0; j < 5; j++) acc[mm][j] = 0.f;

    for (int k0 = 0; k0 < NHID; k0 += 4) {
        float4 wv[5];
        #pragma unroll
        for (int j = 0; j < 5; j++)
            wv[j] = *(const float4*)&w1t[(cg * 5 + j) * HPAD + k0];
        #pragma unroll
        for (int mm = 0; mm < 4; mm++) {
            float4 hv = *(const float4*)&hs[(rg * 4 + mm) * HPAD + k0];
            #pragma unroll
            for (int j = 0; j < 5; j++)
                acc[mm][j] += hv.x * wv[j].x + hv.y * wv[j].y
                            + hv.z * wv[j].z + hv.w * wv[j].w;
        }
    }
    #pragma unroll
    for (int mm = 0; mm < 4; mm++)
        #pragma unroll
        for (int j = 0; j < 5; j++)
            slog[(rg * 4 + mm) * NCLASS + cg * 5 + j] = acc[mm][j] + b1[cg * 5 + j];
    __syncthreads();

    if (tid < HROWS) {
        int gr = row0 + tid;
        if (gr < N) {
            const float* l = slog + tid * NCLASS;
            float m = -1e30f;
            #pragma unroll 8
            for (int c = 0; c < NCLASS; c++) m = fmaxf(m, l[c]);
            float s = 0.f;
            #pragma unroll 8
            for (int c = 0; c < NCLASS; c++) s += expf(l[c] - m);
            float nrm = m + logf(s);
            float* o = out + (size_t)gr * NCLASS;
            #pragma unroll 8
            for (int c = 0; c < NCLASS; c++) o[c] = l[c] - nrm;
        }
    }
}

// ==========================================================================
// host driver — stream fork: build_ell || (prep + h0 GEMM)
// ==========================================================================
extern "C" void kernel_launch(void* const* d_in, const int* in_sizes, int n_in,
                              void* d_out, int out_size) {
    const float* x      = (const float*)d_in[0];
    const float* adj    = (const float*)d_in[1];
    const float* w0     = (const float*)d_in[2];
    const float* b0     = (const float*)d_in[3];
    const float* conv_w = (const float*)d_in[4];
    const float* w1     = (const float*)d_in[5];
    const float* b1     = (const float*)d_in[6];
    float* out = (float*)d_out;

    float *p_h, *p_support;
    __half *p_Bimg, *p_B0img, *p_x16, *p_h016, *p_h16, *p_sup16;
    cudaGetSymbolAddress((void**)&p_h, g_h);
    cudaGetSymbolAddress((void**)&p_support, g_support);
    cudaGetSymbolAddress((void**)&p_Bimg, g_Bimg);
    cudaGetSymbolAddress((void**)&p_B0img, g_B0img);
    cudaGetSymbolAddress((void**)&p_x16, g_x16);
    cudaGetSymbolAddress((void**)&p_h016, g_h0_16);
    cudaGetSymbolAddress((void**)&p_h16, g_h16);
    cudaGetSymbolAddress((void**)&p_sup16, g_sup16);

    static cudaStream_t s1 = nullptr;
    static cudaEvent_t evFork = nullptr, evJoin = nullptr;
    static int head_smem = 0;
    if (!s1) {
        cudaStreamCreate(&s1);
        cudaEventCreateWithFlags(&evFork, cudaEventDisableTiming);
        cudaEventCreateWithFlags(&evJoin, cudaEventDisableTiming);
        head_smem = (NCLASS * HPAD + HROWS * HPAD + HROWS * NCLASS) * 4;
        cudaFuncSetAttribute(head_kernel, cudaFuncAttributeMaxDynamicSharedMemorySize, head_smem);
    }

    // fork: build_ell on s1, concurrent with prep + h0 GEMM on main stream
    cudaEventRecord(evFork, 0);
    cudaStreamWaitEvent(s1, evFork, 0);
    build_ell_kernel<<<N, 256, 0, s1>>>(adj);
    cudaEventRecord(evJoin, s1);

    prep_all_kernel<<<(N * NFEAT + 255) / 256, 256>>>(x, conv_w, w0);

    dim3 gg((N + 63) / 64, 4);
    // h0 = relu(x @ w0 + b0): fp16 image only (fp32 h0 never consumed)
    gemm_hmma_kernel<<<gg, 128>>>(p_x16, N, NFEAT, p_B0img, nullptr, p_h016,
                                  b0, nullptr, 0.f, 0.f, 0);

    cudaStreamWaitEvent(0, evJoin, 0);   // join before first spmm

    const __half2* hcur2 = (const __half2*)p_h016;
    for (int l = 0; l < NLAYERS; l++) {
        float theta = logf(0.5f / (float)(l + 1) + 1.0f);
        float rtheta = 1.0f - theta;
        spmm_support_kernel<<<N, 128>>>(hcur2, (const __half2*)p_h016,
                                        p_support, (__half2*)p_sup16);
        // fp32 output only needed for the last layer (head input)
        float* cdst = (l == NLAYERS - 1) ? p_h : nullptr;
        gemm_hmma_kernel<<<gg, 128>>>(p_sup16, N, NHID,
                                      p_Bimg + (size_t)l * 65536, cdst, p_h16,
                                      nullptr, p_support, theta, rtheta, 1);
        hcur2 = (const __half2*)p_h16;
    }

    head_kernel<<<(N + HROWS - 1) / HROWS, 128, head_smem>>>(p_h, w1, b1, out);
}

// round 7
// speedup vs baseline: 2.4122x; 1.0248x over previous
#include <cuda_runtime.h>
#include <cuda_fp16.h>
#include <math.h>
#include <stdint.h>

#define N       10000
#define NFEAT   512
#define NHID    256
#define NCLASS  40
#define NLAYERS 8
#define MAXW    128
#define WSEG    164

// ---------------- device scratch (no allocation allowed) ----------------
__device__ float g_dinv[N];
__device__ int   g_rowlen[N];
__device__ int   g_cols[(size_t)N * MAXW];
__device__ float g_h[(size_t)N * NHID];
__device__ __align__(16) __half g_x16[(size_t)N * NFEAT];
__device__ __align__(16) __half g_h0_16[(size_t)N * NHID];
__device__ __align__(16) __half g_h16[(size_t)N * NHID];
__device__ __align__(16) __half g_sup16[(size_t)N * NHID];
__device__ __align__(16) __half g_Bimg[(size_t)NLAYERS * NHID * NHID];
__device__ __align__(16) __half g_B0img[(size_t)NFEAT * NHID];

__device__ __forceinline__ uint32_t smem_u32(const void* p) {
    uint32_t a;
    asm("{ .reg .u64 t; cvta.to.shared.u64 t, %1; cvt.u32.u64 %0, t; }" : "=r"(a) : "l"(p));
    return a;
}
__device__ __host__ __forceinline__ uint32_t swz(uint32_t off) {
    return off ^ ((off >> 3) & 0x70);
}

// ==========================================================================
// merged prep
// ==========================================================================
__global__ void prep_all_kernel(const float* __restrict__ x,
                                const float* __restrict__ conv_w,
                                const float* __restrict__ w0) {
    int i = blockIdx.x * 256 + threadIdx.x;
    if (i < N * NFEAT) g_x16[i] = __float2half_rn(x[i]);
    if (i < NLAYERS * NHID * NHID) {
        int n = i & 255, k = (i >> 8) & 255, l = i >> 16;
        int ntile = n >> 6, nl = n & 63, kc = k >> 5, kk = k & 31;
        char* blk = (char*)(g_Bimg + (size_t)l * 65536) + ((size_t)(ntile * 8 + kc)) * 4096;
        *(__half*)(blk + swz(nl * 64 + kk * 2)) = __float2half_rn(conv_w[i]);
    }
    if (i < NFEAT * NHID) {
        int n = i & 255, k = i >> 8;
        int ntile = n >> 6, nl = n & 63, kc = k >> 5, kk = k & 31;
        char* blk = (char*)g_B0img + ((size_t)(ntile * 16 + kc)) * 4096;
        *(__half*)(blk + swz(nl * 64 + kk * 2)) = __float2half_rn(w0[i]);
    }
}

// ==========================================================================
// build_ell v5: depth-4 register prefetch pipeline (MLP=4)
// ==========================================================================
__device__ __forceinline__ float4 ell_load(const float* row, int chunk, int lane) {
    int c = chunk * 128 + lane * 4;
    float4 v = make_float4(0.f, 0.f, 0.f, 0.f);
    if (c + 3 < N) {
        v = __ldcs((const float4*)(row + c));
    } else {
        if (c + 0 < N) v.x = row[c + 0];
        if (c + 1 < N) v.y = row[c + 1];
        if (c + 2 < N) v.z = row[c + 2];
        if (c + 3 < N) v.w = row[c + 3];
    }
    return v;
}

__global__ __launch_bounds__(256)
void build_ell_kernel(const float* __restrict__ adj) {
    int i = blockIdx.x;
    const float* row = adj + (size_t)i * N;
    int tid = threadIdx.x, lane = tid & 31, w = tid >> 5;
    __shared__ int s_idx[8][WSEG];
    __shared__ int s_cnt[8];
    __shared__ int s_off[8];
    unsigned lt = (1u << lane) - 1u;
    int base = 0;

    #define ELL_PROC(v, chunk) do { \
        int c = (chunk) * 128 + lane * 4; \
        unsigned b0 = __ballot_sync(0xffffffffu, (v).x != 0.f); \
        unsigned b1 = __ballot_sync(0xffffffffu, (v).y != 0.f); \
        unsigned b2 = __ballot_sync(0xffffffffu, (v).z != 0.f); \
        unsigned b3 = __ballot_sync(0xffffffffu, (v).w != 0.f); \
        if (b0 | b1 | b2 | b3) { \
            int o1 = base + __popc(b0); \
            int o2 = o1 + __popc(b1); \
            int o3 = o2 + __popc(b2); \
            int p; \
            p = base + __popc(b0 & lt); \
            if (((v).x != 0.f) && p < WSEG) s_idx[w][p] = c; \
            p = o1 + __popc(b1 & lt); \
            if (((v).y != 0.f) && p < WSEG) s_idx[w][p] = c + 1; \
            p = o2 + __popc(b2 & lt); \
            if (((v).z != 0.f) && p < WSEG) s_idx[w][p] = c + 2; \
            p = o3 + __popc(b3 & lt); \
            if (((v).w != 0.f) && p < WSEG) s_idx[w][p] = c + 3; \
            base = o3 + __popc(b3); \
        } \
    } while (0)

    // depth-4 software pipeline over this warp's chunks (w, w+8, w+16, ...)
    float4 buf[4];
    int pc = w;   // next chunk to prefetch
    #pragma unroll
    for (int d = 0; d < 4; d++) {
        buf[d] = (pc < 79) ? ell_load(row, pc, lane) : make_float4(0.f, 0.f, 0.f, 0.f);
        pc += 8;
    }
    int cur = w;
    for (int it = 0; cur < 79; it++, cur += 8) {
        float4 v = buf[it & 3];
        if (pc < 79) buf[it & 3] = ell_load(row, pc, lane);
        pc += 8;
        ELL_PROC(v, cur);
    }

    if (lane == 0) s_cnt[w] = base < WSEG ? base : WSEG;
    __syncthreads();
    if (tid == 0) {
        int o = 0;
        #pragma unroll
        for (int j = 0; j < 8; j++) { s_off[j] = o; o += s_cnt[j]; }
    }
    __syncthreads();
    int rowoff = i * MAXW;
    int cw = s_cnt[w];
    for (int t = lane; t < cw; t += 32) {
        int pos = s_off[w] + t;
        if (pos < MAXW - 1) g_cols[rowoff + pos] = s_idx[w][t];
    }
    if (tid == 0) {
        int total = s_off[7] + s_cnt[7];
        if (total > MAXW - 1) total = MAXW - 1;
        g_cols[rowoff + total] = i;
        g_rowlen[i] = total + 1;
        g_dinv[i] = rsqrtf((float)(total + 1));
    }
}

// ==========================================================================
// HMMA fp16 GEMM: tile 64x64, BK=64, 128 thr. fp16 residual, optional fp32 C.
// ==========================================================================
#define CP_ASYNC16(dst, src, sz) \
    asm volatile("cp.async.cg.shared.global [%0], [%1], 16, %2;" \
                 :: "r"(dst), "l"(src), "r"(sz))
#define CP_COMMIT() asm volatile("cp.async.commit_group;")
#define CP_WAIT1()  asm volatile("cp.async.wait_group 1;")

__global__ __launch_bounds__(128, 6)
void gemm_hmma_kernel(const __half* __restrict__ A, int M, int K,
                      const __half* __restrict__ Bimg,
                      float* __restrict__ C,             // may be null
                      __half* __restrict__ C16,
                      const float* __restrict__ bias,
                      const __half* __restrict__ resid16,
                      float theta, float rtheta, int mode) {
    __shared__ __align__(128) __half sA[2][64 * 64];
    __shared__ __align__(128) __half sB[2][64 * 64];
    int tid = threadIdx.x, lane = tid & 31, wid = tid >> 5;
    int wm = wid & 1, wn = wid >> 1;
    int bm = blockIdx.x * 64;
    int nc0 = blockIdx.y * 64;
    const __half* Bsrc = Bimg + (size_t)blockIdx.y * (K >> 5) * 2048;
    int nch = K >> 6;

    uint32_t sAb = smem_u32(sA), sBb = smem_u32(sB);

    float acc[2][4][4];
    #pragma unroll
    for (int i = 0; i < 2; i++)
        #pragma unroll
        for (int j = 0; j < 4; j++)
            #pragma unroll
            for (int r = 0; r < 4; r++) acc[i][j][r] = 0.f;

    int rowA = wm * 32 + (lane & 15);
    int colA = (lane >> 4) * 16;
    int rowB = wn * 32 + (lane & 7) + ((lane & 16) ? 8 : 0);
    int colB = ((lane >> 3) & 1) * 16;

    #define STAGE(c, buf) do { \
        int _c = (c), _b = (buf); \
        for (int t = tid; t < 512; t += 128) { \
            int row = t >> 3, j = t & 7; \
            uint32_t dst = sAb + _b * 8192 + swz(row * 128 + j * 16); \
            int gr = bm + row; \
            const __half* src = A + (size_t)(gr < M ? gr : 0) * K + _c * 64 + j * 8; \
            CP_ASYNC16(dst, src, (gr < M) ? 16 : 0); \
        } \
        for (int t = tid; t < 512; t += 128) { \
            uint32_t dst = sBb + _b * 8192 + t * 16; \
            const __half* src = Bsrc + (size_t)_c * 4096 + t * 8; \
            CP_ASYNC16(dst, src, 16); \
        } \
    } while (0)

    STAGE(0, 0);
    CP_COMMIT();

    for (int c = 0; c < nch; c++) {
        if (c + 1 < nch) STAGE(c + 1, (c + 1) & 1);
        CP_COMMIT();
        CP_WAIT1();
        __syncthreads();

        uint32_t aB = sAb + (c & 1) * 8192;
        uint32_t bB = sBb + (c & 1) * 8192;
        #pragma unroll
        for (int s = 0; s < 4; s++) {
            uint32_t a[2][4];
            uint32_t b[4][2];
            #pragma unroll
            for (int mm = 0; mm < 2; mm++) {
                uint32_t addr = aB + swz((rowA + mm * 16) * 128 + s * 32 + colA);
                asm volatile("ldmatrix.sync.aligned.m8n8.x4.shared.b16 {%0,%1,%2,%3}, [%4];"
                    : "=r"(a[mm][0]), "=r"(a[mm][1]), "=r"(a[mm][2]), "=r"(a[mm][3])
                    : "r"(addr));
            }
            #pragma unroll
            for (int p = 0; p < 2; p++) {
                uint32_t addr = bB + (s >> 1) * 4096
                              + swz((rowB + p * 16) * 64 + (s & 1) * 32 + colB);
                asm volatile("ldmatrix.sync.aligned.m8n8.x4.shared.b16 {%0,%1,%2,%3}, [%4];"
                    : "=r"(b[2 * p][0]), "=r"(b[2 * p][1]),
                      "=r"(b[2 * p + 1][0]), "=r"(b[2 * p + 1][1])
                    : "r"(addr));
            }
            #pragma unroll
            for (int mm = 0; mm < 2; mm++)
                #pragma unroll
                for (int nf = 0; nf < 4; nf++)
                    asm volatile(
                        "mma.sync.aligned.m16n8k16.row.col.f32.f16.f16.f32 "
                        "{%0,%1,%2,%3}, {%4,%5,%6,%7}, {%8,%9}, {%0,%1,%2,%3};"
                        : "+f"(acc[mm][nf][0]), "+f"(acc[mm][nf][1]),
                          "+f"(acc[mm][nf][2]), "+f"(acc[mm][nf][3])
                        : "r"(a[mm][0]), "r"(a[mm][1]), "r"(a[mm][2]), "r"(a[mm][3]),
                          "r"(b[nf][0]), "r"(b[nf][1]));
        }
        __syncthreads();
    }

    int quad = lane >> 2, tq = lane & 3;
    #pragma unroll
    for (int mm = 0; mm < 2; mm++) {
        #pragma unroll
        for (int half = 0; half < 2; half++) {
            int grow = bm + wm * 32 + mm * 16 + quad + half * 8;
            if (grow >= M) continue;
            #pragma unroll
            for (int nf = 0; nf < 4; nf++) {
                int nc = nc0 + wn * 32 + nf * 8 + tq * 2;
                float v0 = acc[mm][nf][half * 2 + 0];
                float v1 = acc[mm][nf][half * 2 + 1];
                float o0, o1;
                if (mode == 0) {
                    o0 = fmaxf(v0 + bias[nc], 0.f);
                    o1 = fmaxf(v1 + bias[nc + 1], 0.f);
                } else {
                    float2 r = __half22float2(
                        *(const __half2*)(resid16 + (size_t)grow * NHID + nc));
                    o0 = fmaxf(theta * v0 + rtheta * r.x, 0.f);
                    o1 = fmaxf(theta * v1 + rtheta * r.y, 0.f);
                }
                if (C) *(float2*)(C + (size_t)grow * NHID + nc) = make_float2(o0, o1);
                *(__half2*)(C16 + (size_t)grow * NHID + nc) = __floats2half2_rn(o0, o1);
            }
        }
    }
}

// ==========================================================================
// SpMM v3: split-K halves, uint2 (4-feature) gathers, fp16-only output.
// 128 threads: g = tid&63 feature group, hlf = tid>>6 neighbor half.
// ==========================================================================
__global__ __launch_bounds__(128)
void spmm_support_kernel(const uint2* __restrict__ hv,     // h16 rows as 64 x uint2
                         const uint2* __restrict__ h0v,    // h0 rows as 64 x uint2
                         uint2* __restrict__ supv) {       // sup16 rows as 64 x uint2
    int i = blockIdx.x, tid = threadIdx.x;
    __shared__ float s_w[MAXW];
    __shared__ int   s_c[MAXW];
    __shared__ float s_part[64][4];
    int len = g_rowlen[i];
    if (tid < len) {
        int c = g_cols[i * MAXW + tid];
        s_c[tid] = c * 64;
        s_w[tid] = g_dinv[c];
    }
    __syncthreads();
    int g = tid & 63, hlf = tid >> 6;
    int lhalf = (len + 1) >> 1;
    int k0 = hlf ? lhalf : 0;
    int k1 = hlf ? len : lhalf;
    float a0 = 0.f, a1 = 0.f, a2 = 0.f, a3 = 0.f;
    #pragma unroll 4
    for (int k = k0; k < k1; k++) {
        uint2 u = __ldg(&hv[s_c[k] + g]);
        float2 f0 = __half22float2(*(__half2*)&u.x);
        float2 f1 = __half22float2(*(__half2*)&u.y);
        float wv = s_w[k];
        a0 += wv * f0.x; a1 += wv * f0.y;
        a2 += wv * f1.x; a3 += wv * f1.y;
    }
    if (hlf) {
        s_part[g][0] = a0; s_part[g][1] = a1;
        s_part[g][2] = a2; s_part[g][3] = a3;
    }
    __syncthreads();
    if (!hlf) {
        a0 += s_part[g][0]; a1 += s_part[g][1];
        a2 += s_part[g][2]; a3 += s_part[g][3];
        float di = 0.9f * g_dinv[i];
        uint2 r = __ldg(&h0v[i * 64 + g]);
        float2 r0 = __half22float2(*(__half2*)&r.x);
        float2 r1 = __half22float2(*(__half2*)&r.y);
        float o0 = di * a0 + 0.1f * r0.x;
        float o1 = di * a1 + 0.1f * r0.y;
        float o2 = di * a2 + 0.1f * r1.x;
        float o3 = di * a3 + 0.1f * r1.y;
        __half2 q0 = __floats2half2_rn(o0, o1);
        __half2 q1 = __floats2half2_rn(o2, o3);
        uint2 wv2;
        wv2.x = *(unsigned*)&q0;
        wv2.y = *(unsigned*)&q1;
        supv[i * 64 + g] = wv2;
    }
}

// ==========================================================================
// head: 64 rows/block, 128 threads, register tiled 4x5
// ==========================================================================
#define HPAD 260
#define HROWS 64
__global__ __launch_bounds__(128)
void head_kernel(const float* __restrict__ h,
                 const float* __restrict__ w1,
                 const float* __restrict__ b1,
                 float* __restrict__ out) {
    extern __shared__ float sm[];
    float* w1t = sm;
    float* hs  = sm + NCLASS * HPAD;
    float* slog = hs + HROWS * HPAD;

    int tid = threadIdx.x;
    int row0 = blockIdx.x * HROWS;

    for (int t = tid; t < NHID * NCLASS; t += 128) {
        int k = t / NCLASS, c = t % NCLASS;
        w1t[c * HPAD + k] = w1[t];
    }
    for (int t = tid; t < HROWS * NHID; t += 128) {
        int r = t >> 8, k = t & 255;
        int gr = row0 + r;
        hs[r * HPAD + k] = (gr < N) ? h[(size_t)gr * NHID + k] : 0.f;
    }
    __syncthreads();

    int cg = tid & 7;
    int rg = tid >> 3;
    float acc[4][5];
    #pragma unroll
    for (int mm = 0; mm < 4; mm++)
        #pragma unroll
        for (int j = 0; j < 5; j++) acc[mm][j] = 0.f;

    for (int k0 = 0; k0 < NHID; k0 += 4) {
        float4 wv[5];
        #pragma unroll
        for (int j = 0; j < 5; j++)
            wv[j] = *(const float4*)&w1t[(cg * 5 + j) * HPAD + k0];
        #pragma unroll
        for (int mm = 0; mm < 4; mm++) {
            float4 hvv = *(const float4*)&hs[(rg * 4 + mm) * HPAD + k0];
            #pragma unroll
            for (int j = 0; j < 5; j++)
                acc[mm][j] += hvv.x * wv[j].x + hvv.y * wv[j].y
                            + hvv.z * wv[j].z + hvv.w * wv[j].w;
        }
    }
    #pragma unroll
    for (int mm = 0; mm < 4; mm++)
        #pragma unroll
        for (int j = 0; j < 5; j++)
            slog[(rg * 4 + mm) * NCLASS + cg * 5 + j] = acc[mm][j] + b1[cg * 5 + j];
    __syncthreads();

    if (tid < HROWS) {
        int gr = row0 + tid;
        if (gr < N) {
            const float* l = slog + tid * NCLASS;
            float m = -1e30f;
            #pragma unroll 8
            for (int c = 0; c < NCLASS; c++) m = fmaxf(m, l[c]);
            float s = 0.f;
            #pragma unroll 8
            for (int c = 0; c < NCLASS; c++) s += expf(l[c] - m);
            float nrm = m + logf(s);
            float* o = out + (size_t)gr * NCLASS;
            #pragma unroll 8
            for (int c = 0; c < NCLASS; c++) o[c] = l[c] - nrm;
        }
    }
}

// ==========================================================================
// host driver — stream fork: build_ell || (prep + h0 GEMM)
// ==========================================================================
extern "C" void kernel_launch(void* const* d_in, const int* in_sizes, int n_in,
                              void* d_out, int out_size) {
    const float* x      = (const float*)d_in[0];
    const float* adj    = (const float*)d_in[1];
    const float* w0     = (const float*)d_in[2];
    const float* b0     = (const float*)d_in[3];
    const float* conv_w = (const float*)d_in[4];
    const float* w1     = (const float*)d_in[5];
    const float* b1     = (const float*)d_in[6];
    float* out = (float*)d_out;

    float *p_h;
    __half *p_Bimg, *p_B0img, *p_x16, *p_h016, *p_h16, *p_sup16;
    cudaGetSymbolAddress((void**)&p_h, g_h);
    cudaGetSymbolAddress((void**)&p_Bimg, g_Bimg);
    cudaGetSymbolAddress((void**)&p_B0img, g_B0img);
    cudaGetSymbolAddress((void**)&p_x16, g_x16);
    cudaGetSymbolAddress((void**)&p_h016, g_h0_16);
    cudaGetSymbolAddress((void**)&p_h16, g_h16);
    cudaGetSymbolAddress((void**)&p_sup16, g_sup16);

    static cudaStream_t s1 = nullptr;
    static cudaEvent_t evFork = nullptr, evJoin = nullptr;
    static int head_smem = 0;
    if (!s1) {
        cudaStreamCreate(&s1);
        cudaEventCreateWithFlags(&evFork, cudaEventDisableTiming);
        cudaEventCreateWithFlags(&evJoin, cudaEventDisableTiming);
        head_smem = (NCLASS * HPAD + HROWS * HPAD + HROWS * NCLASS) * 4;
        cudaFuncSetAttribute(head_kernel, cudaFuncAttributeMaxDynamicSharedMemorySize, head_smem);
    }

    cudaEventRecord(evFork, 0);
    cudaStreamWaitEvent(s1, evFork, 0);
    build_ell_kernel<<<N, 256, 0, s1>>>(adj);
    cudaEventRecord(evJoin, s1);

    prep_all_kernel<<<(N * NFEAT + 255) / 256, 256>>>(x, conv_w, w0);

    dim3 gg((N + 63) / 64, 4);
    gemm_hmma_kernel<<<gg, 128>>>(p_x16, N, NFEAT, p_B0img, nullptr, p_h016,
                                  b0, nullptr, 0.f, 0.f, 0);

    cudaStreamWaitEvent(0, evJoin, 0);

    const __half* hcur = p_h016;
    for (int l = 0; l < NLAYERS; l++) {
        float theta = logf(0.5f / (float)(l + 1) + 1.0f);
        float rtheta = 1.0f - theta;
        spmm_support_kernel<<<N, 128>>>((const uint2*)hcur, (const uint2*)p_h016,
                                        (uint2*)p_sup16);
        float* cdst = (l == NLAYERS - 1) ? p_h : nullptr;
        gemm_hmma_kernel<<<gg, 128>>>(p_sup16, N, NHID,
                                      p_Bimg + (size_t)l * 65536, cdst, p_h16,
                                      nullptr, p_sup16, theta, rtheta, 1);
        hcur = p_h16;
    }

    head_kernel<<<(N + HROWS - 1) / HROWS, 128, head_smem>>>(p_h, w1, b1, out);
}